// round 1
// baseline (speedup 1.0000x reference)
#include <cuda_runtime.h>
#include <math.h>

// Problem shape (fixed by setup_inputs): n=2, l=2048, d_model=1024, h=16, e=64
#define NB 2
#define SEQL 2048
#define DM 1024
#define NH 16
#define DE 64
#define ROWS (NB * SEQL)          // 4096

// ---------------- scratch (static __device__, no allocs) ----------------
__device__ float g_cw[NB * DM];               // cond @ w_cond + 1
__device__ float g_xn[ROWS * DM];             // rms-normed x
__device__ float g_qkv[ROWS * 3 * DM];        // xn @ w_qkv
__device__ float g_Q[NB * NH * SEQL * DE];
__device__ float g_K[NB * NH * SEQL * DE];
__device__ float g_V[NB * NH * SEQL * DE];
__device__ float g_O[ROWS * DM];              // attention out, (n,l,h*e)

// ---------------- kernel 1: cw = cond @ w_cond + 1 ----------------
__global__ void cond_gemm_kernel(const float* __restrict__ cond,
                                 const float* __restrict__ w_cond)
{
    __shared__ float cs[DM];
    const int n = blockIdx.y;
    for (int k = threadIdx.x; k < DM; k += blockDim.x)
        cs[k] = cond[n * DM + k];
    __syncthreads();

    const int j = blockIdx.x * blockDim.x + threadIdx.x;
    float acc = 0.f;
#pragma unroll 8
    for (int k = 0; k < DM; k++)
        acc = fmaf(cs[k], w_cond[k * DM + j], acc);
    g_cw[n * DM + j] = acc + 1.0f;
}

// ---------------- kernel 2: xn = rms_norm(x, cw) ----------------
__global__ void rmsnorm_x_kernel(const float* __restrict__ x)
{
    const int row = blockIdx.x;           // 0..4095 = (n, l)
    const int n = row / SEQL;
    const int t = threadIdx.x;            // 256 threads, 4 floats each

    float4 v = *(const float4*)(x + (size_t)row * DM + t * 4);
    float ss = v.x * v.x + v.y * v.y + v.z * v.z + v.w * v.w;
#pragma unroll
    for (int o = 16; o > 0; o >>= 1)
        ss += __shfl_xor_sync(0xffffffffu, ss, o);

    __shared__ float ws[8];
    if ((t & 31) == 0) ws[t >> 5] = ss;
    __syncthreads();
    float tot = ws[0] + ws[1] + ws[2] + ws[3] + ws[4] + ws[5] + ws[6] + ws[7];
    float rinv = rsqrtf(tot * (1.0f / DM) + 1e-6f);

    float4 cwv = *(const float4*)(g_cw + n * DM + t * 4);
    float4 o;
    o.x = v.x * cwv.x * rinv;
    o.y = v.y * cwv.y * rinv;
    o.z = v.z * cwv.z * rinv;
    o.w = v.w * cwv.w * rinv;
    *(float4*)(g_xn + (size_t)row * DM + t * 4) = o;
}

// ---------------- generic tiled SGEMM: C[M,N] = A[M,K] @ B[K,N] ----------------
// BM=128, BN=128, BK=16, 256 threads, 8x8 per-thread register tile.
__global__ __launch_bounds__(256) void sgemm_kernel(
    const float* __restrict__ A, const float* __restrict__ B,
    float* __restrict__ C, int M, int N, int K)
{
    const int BM = 128, BN = 128, BK = 16, TM = 8, TN = 8;
    __shared__ float As[BK][BM];
    __shared__ float Bs[BK][BN];

    const int tid  = threadIdx.x;
    const int tcol = tid % (BN / TN);   // 0..15
    const int trow = tid / (BN / TN);   // 0..15
    const int rowA0 = blockIdx.y * BM;
    const int colB0 = blockIdx.x * BN;

    const int a_row  = tid >> 2;            // 0..63
    const int a_col  = (tid & 3) * 4;       // 0,4,8,12
    const int b_row  = tid >> 5;            // 0..7
    const int b_col  = (tid & 31) * 4;      // 0..124

    float acc[TM][TN];
#pragma unroll
    for (int i = 0; i < TM; i++)
#pragma unroll
        for (int j = 0; j < TN; j++) acc[i][j] = 0.f;

    for (int k0 = 0; k0 < K; k0 += BK) {
#pragma unroll
        for (int i = 0; i < 2; i++) {
            int r = a_row + i * 64;
            float4 v = *(const float4*)(A + (size_t)(rowA0 + r) * K + k0 + a_col);
            As[a_col + 0][r] = v.x;
            As[a_col + 1][r] = v.y;
            As[a_col + 2][r] = v.z;
            As[a_col + 3][r] = v.w;
        }
#pragma unroll
        for (int i = 0; i < 2; i++) {
            int r = b_row + i * 8;
            float4 v = *(const float4*)(B + (size_t)(k0 + r) * N + colB0 + b_col);
            *(float4*)(&Bs[r][b_col]) = v;
        }
        __syncthreads();

#pragma unroll
        for (int k = 0; k < BK; k++) {
            float ar[TM], br[TN];
            float4 a0 = *(const float4*)(&As[k][trow * TM]);
            float4 a1 = *(const float4*)(&As[k][trow * TM + 4]);
            ar[0]=a0.x; ar[1]=a0.y; ar[2]=a0.z; ar[3]=a0.w;
            ar[4]=a1.x; ar[5]=a1.y; ar[6]=a1.z; ar[7]=a1.w;
            float4 b0 = *(const float4*)(&Bs[k][tcol * TN]);
            float4 b1 = *(const float4*)(&Bs[k][tcol * TN + 4]);
            br[0]=b0.x; br[1]=b0.y; br[2]=b0.z; br[3]=b0.w;
            br[4]=b1.x; br[5]=b1.y; br[6]=b1.z; br[7]=b1.w;
#pragma unroll
            for (int i = 0; i < TM; i++)
#pragma unroll
                for (int j = 0; j < TN; j++)
                    acc[i][j] = fmaf(ar[i], br[j], acc[i][j]);
        }
        __syncthreads();
    }

#pragma unroll
    for (int i = 0; i < TM; i++) {
        int r = rowA0 + trow * TM + i;
#pragma unroll
        for (int j = 0; j < TN; j += 4) {
            float4 v = make_float4(acc[i][j], acc[i][j+1], acc[i][j+2], acc[i][j+3]);
            *(float4*)(C + (size_t)r * N + colB0 + tcol * TN + j) = v;
        }
    }
}

// ---------------- kernel 4: per-head qk rmsnorm + axial rope + scatter ----------------
// grid(ROWS, 4), 128 threads: warp w handles head = blockIdx.y*4 + w.
// lane i owns channel pair (i, i+32) -> exactly the rotary pair.
__global__ void qknorm_rope_kernel(const float* __restrict__ pos,
                                   const float* __restrict__ qk_scale)
{
    const int row  = blockIdx.x;               // (n, l)
    const int n    = row / SEQL;
    const int l    = row % SEQL;
    const int warp = threadIdx.x >> 5;
    const int lane = threadIdx.x & 31;
    const int head = blockIdx.y * 4 + warp;

    const float* base = g_qkv + (size_t)row * (3 * DM);
    const int d1 = lane, d2 = lane + 32;

    float qa = base[head * DE + d1],          qb = base[head * DE + d2];
    float ka = base[DM + head * DE + d1],     kb = base[DM + head * DE + d2];
    float va = base[2 * DM + head * DE + d1], vb = base[2 * DM + head * DE + d2];

    float ssq = qa * qa + qb * qb;
    float ssk = ka * ka + kb * kb;
#pragma unroll
    for (int o = 16; o > 0; o >>= 1) {
        ssq += __shfl_xor_sync(0xffffffffu, ssq, o);
        ssk += __shfl_xor_sync(0xffffffffu, ssk, o);
    }

    // s = exp(0.5*min(qk_scale, log 100) - 0.25*log(64))
    float sc = expf(0.5f * fminf(qk_scale[head], 4.6051701860f) - 1.0397207708f);
    float rq = sc * rsqrtf(ssq * (1.0f / DE) + 1e-6f);
    float rk = sc * rsqrtf(ssk * (1.0f / DE) + 1e-6f);
    qa *= rq; qb *= rq; ka *= rk; kb *= rk;

    // theta: lanes 0..15 use pos0 with freq index j=lane; 16..31 use pos1, j=lane-16
    // freqs[h][j] = exp(log(pi) + (j*16 + h) * log(10)/256)
    float pv = pos[(size_t)row * 2 + (lane >> 4)];
    int   j  = lane & 15;
    float fr = expf(1.14472988584940017f + (float)(j * 16 + head) * (2.30258509299404568f / 256.0f));
    float th = pv * fr;
    float cth = cosf(th), sth = sinf(th);

    float qo1 = qa * cth - qb * sth, qo2 = qb * cth + qa * sth;
    float ko1 = ka * cth - kb * sth, ko2 = kb * cth + ka * sth;

    size_t ob = ((size_t)(n * NH + head) * SEQL + l) * DE;
    g_Q[ob + d1] = qo1; g_Q[ob + d2] = qo2;
    g_K[ob + d1] = ko1; g_K[ob + d2] = ko2;
    g_V[ob + d1] = va;  g_V[ob + d2] = vb;
}

// ---------------- kernel 5: flash attention, one query row per thread ----------------
#define FA_BM 128
#define FA_BN 32
__global__ __launch_bounds__(128, 2) void flash_attn_kernel()
{
    const int qb    = blockIdx.x;
    const int head  = blockIdx.y;
    const int batch = blockIdx.z;
    const int t     = threadIdx.x;

    const size_t bh = (size_t)(batch * NH + head) * SEQL * DE;
    const float* Qp = g_Q + bh;
    const float* Kp = g_K + bh;
    const float* Vp = g_V + bh;
    const int qrow  = qb * FA_BM + t;

    float q[DE];
#pragma unroll
    for (int d = 0; d < DE; d += 4) {
        float4 v = *(const float4*)(Qp + (size_t)qrow * DE + d);
        q[d] = v.x; q[d+1] = v.y; q[d+2] = v.z; q[d+3] = v.w;
    }
    float acc[DE];
#pragma unroll
    for (int d = 0; d < DE; d++) acc[d] = 0.f;
    float m = -1e30f, lsum = 0.f;

    __shared__ float Ks[FA_BN][DE];
    __shared__ float Vs[FA_BN][DE];

    for (int kb = 0; kb < SEQL; kb += FA_BN) {
        __syncthreads();
        // K/V tile: 32*64 = 2048 floats = 512 float4 each; 128 threads x 4
#pragma unroll
        for (int i = 0; i < 4; i++) {
            int fid = i * 128 + t;            // 0..511
            int r = fid >> 4;
            int c = (fid & 15) * 4;
            *(float4*)(&Ks[r][c]) = *(const float4*)(Kp + (size_t)(kb + r) * DE + c);
            *(float4*)(&Vs[r][c]) = *(const float4*)(Vp + (size_t)(kb + r) * DE + c);
        }
        __syncthreads();

        float s[FA_BN];
        float tmax = -1e30f;
#pragma unroll
        for (int jj = 0; jj < FA_BN; jj++) {
            float sj = 0.f;
#pragma unroll
            for (int d = 0; d < DE; d++)
                sj = fmaf(q[d], Ks[jj][d], sj);
            sj *= 0.125f;                      // 1/sqrt(64)
            s[jj] = sj;
            tmax = fmaxf(tmax, sj);
        }
        float mnew = fmaxf(m, tmax);
        float corr = __expf(m - mnew);
        lsum *= corr;
#pragma unroll
        for (int d = 0; d < DE; d++) acc[d] *= corr;
#pragma unroll
        for (int jj = 0; jj < FA_BN; jj++) {
            float p = __expf(s[jj] - mnew);
            lsum += p;
#pragma unroll
            for (int d = 0; d < DE; d++)
                acc[d] = fmaf(p, Vs[jj][d], acc[d]);
        }
        m = mnew;
    }

    float inv = 1.0f / lsum;
    float* Op = g_O + ((size_t)(batch * SEQL + qrow)) * DM + head * DE;
#pragma unroll
    for (int d = 0; d < DE; d += 4) {
        float4 v = make_float4(acc[d] * inv, acc[d+1] * inv, acc[d+2] * inv, acc[d+3] * inv);
        *(float4*)(Op + d) = v;
    }
}

// ---------------- launch ----------------
extern "C" void kernel_launch(void* const* d_in, const int* in_sizes, int n_in,
                              void* d_out, int out_size)
{
    const float* x        = (const float*)d_in[0];
    const float* pos      = (const float*)d_in[1];
    const float* cond     = (const float*)d_in[2];
    const float* w_cond   = (const float*)d_in[3];
    const float* w_qkv    = (const float*)d_in[4];
    const float* qk_scale = (const float*)d_in[5];
    const float* w_out    = (const float*)d_in[6];
    float* out = (float*)d_out;

    float *p_xn, *p_qkv, *p_O;
    cudaGetSymbolAddress((void**)&p_xn,  g_xn);
    cudaGetSymbolAddress((void**)&p_qkv, g_qkv);
    cudaGetSymbolAddress((void**)&p_O,   g_O);

    // 1. cw = cond @ w_cond + 1
    cond_gemm_kernel<<<dim3(DM / 256, NB), 256>>>(cond, w_cond);
    // 2. xn = rms_norm(x, cw)
    rmsnorm_x_kernel<<<ROWS, 256>>>(x);
    // 3. qkv = xn @ w_qkv   (4096 x 1024 @ 1024 x 3072)
    sgemm_kernel<<<dim3(3 * DM / 128, ROWS / 128), 256>>>(p_xn, w_qkv, p_qkv, ROWS, 3 * DM, DM);
    // 4. per-head qk rmsnorm + rope -> Q, K, V in (n,h,l,e)
    qknorm_rope_kernel<<<dim3(ROWS, NH / 4), 128>>>(pos, qk_scale);
    // 5. attention -> O in (n,l,h*e)
    flash_attn_kernel<<<dim3(SEQL / FA_BM, NH, NB), 128>>>();
    // 6. out = O @ w_out
    sgemm_kernel<<<dim3(DM / 128, ROWS / 128), 256>>>(p_O, w_out, out, ROWS, DM, DM);
}

// round 3
// speedup vs baseline: 2.4982x; 2.4982x over previous
#include <cuda_runtime.h>
#include <cuda_fp16.h>
#include <math.h>
#include <stdint.h>

// Problem shape: n=2, l=2048, d_model=1024, h=16, e=64
#define NB 2
#define SEQL 2048
#define DM 1024
#define NH 16
#define DE 64
#define ROWS (NB * SEQL)          // 4096

// ---------------- scratch ----------------
__device__ float  g_cw[NB * DM];
__device__ float  g_qkv[ROWS * 3 * DM];
__device__ __half g_xnh[ROWS * DM], g_xnl[ROWS * DM];
__device__ __half g_qh[NB*NH*SEQL*DE], g_ql[NB*NH*SEQL*DE];
__device__ __half g_kh[NB*NH*SEQL*DE], g_kl[NB*NH*SEQL*DE];
__device__ __half g_vh[NB*NH*SEQL*DE], g_vl[NB*NH*SEQL*DE];
__device__ __half g_oh[ROWS * DM], g_ol[ROWS * DM];
__device__ __half g_wqh[DM * 3 * DM], g_wql[DM * 3 * DM];
__device__ __half g_woh[DM * DM],     g_wol[DM * DM];

// ---------------- helpers ----------------
static __device__ __forceinline__ uint32_t smem_u32(const void* p) {
    uint32_t a;
    asm("{ .reg .u64 t; cvta.to.shared.u64 t, %1; cvt.u32.u64 %0, t; }" : "=r"(a) : "l"(p));
    return a;
}
static __device__ __forceinline__ void cpasync16(uint32_t dst, const void* src) {
    asm volatile("cp.async.cg.shared.global [%0], [%1], 16;" :: "r"(dst), "l"(src));
}
#define CP_COMMIT() asm volatile("cp.async.commit_group;" ::: "memory")
#define CP_WAIT1()  asm volatile("cp.async.wait_group 1;"  ::: "memory")
static __device__ __forceinline__ void ldsm4(uint32_t* r, uint32_t a) {
    asm volatile("ldmatrix.sync.aligned.m8n8.x4.shared.b16 {%0,%1,%2,%3}, [%4];"
        : "=r"(r[0]), "=r"(r[1]), "=r"(r[2]), "=r"(r[3]) : "r"(a));
}
static __device__ __forceinline__ void ldsm4t(uint32_t* r, uint32_t a) {
    asm volatile("ldmatrix.sync.aligned.m8n8.x4.trans.shared.b16 {%0,%1,%2,%3}, [%4];"
        : "=r"(r[0]), "=r"(r[1]), "=r"(r[2]), "=r"(r[3]) : "r"(a));
}
static __device__ __forceinline__ void mma_f16(float* c, const uint32_t* a, const uint32_t* b) {
    asm volatile("mma.sync.aligned.m16n8k16.row.col.f32.f16.f16.f32 "
        "{%0,%1,%2,%3}, {%4,%5,%6,%7}, {%8,%9}, {%0,%1,%2,%3};"
        : "+f"(c[0]), "+f"(c[1]), "+f"(c[2]), "+f"(c[3])
        : "r"(a[0]), "r"(a[1]), "r"(a[2]), "r"(a[3]), "r"(b[0]), "r"(b[1]));
}
static __device__ __forceinline__ float fast_exp2(float x) {
    float y; asm("ex2.approx.f32 %0, %1;" : "=f"(y) : "f"(x)); return y;
}
static __device__ __forceinline__ void hsplit(float x, __half& h, __half& l) {
    h = __float2half_rn(x);
    l = __float2half_rn(x - __half2float(h));
}
static __device__ __forceinline__ uint32_t packh(__half a, __half b) {
    return (uint32_t)__half_as_ushort(a) | ((uint32_t)__half_as_ushort(b) << 16);
}

// ---------------- kernel: split fp32 -> fp16 hi/lo ----------------
__global__ void split_kernel(const float* __restrict__ s, __half* __restrict__ h,
                             __half* __restrict__ l, int n)
{
    int i = blockIdx.x * blockDim.x + threadIdx.x;
    if (i < n) {
        float v = s[i];
        __half hh = __float2half_rn(v);
        h[i] = hh;
        l[i] = __float2half_rn(v - __half2float(hh));
    }
}

// ---------------- kernel 1: cw = cond @ w_cond + 1 ----------------
__global__ void cond_gemm_kernel(const float* __restrict__ cond,
                                 const float* __restrict__ w_cond)
{
    __shared__ float cs[DM];
    const int n = blockIdx.y;
    for (int k = threadIdx.x; k < DM; k += blockDim.x)
        cs[k] = cond[n * DM + k];
    __syncthreads();
    const int j = blockIdx.x * blockDim.x + threadIdx.x;
    float acc = 0.f;
#pragma unroll 8
    for (int k = 0; k < DM; k++)
        acc = fmaf(cs[k], w_cond[k * DM + j], acc);
    g_cw[n * DM + j] = acc + 1.0f;
}

// ---------------- kernel 2: xn = rms_norm(x, cw) -> fp16 hi/lo ----------------
__global__ void rmsnorm_x_kernel(const float* __restrict__ x)
{
    const int row = blockIdx.x;
    const int n = row / SEQL;
    const int t = threadIdx.x;

    float4 v = *(const float4*)(x + (size_t)row * DM + t * 4);
    float ss = v.x * v.x + v.y * v.y + v.z * v.z + v.w * v.w;
#pragma unroll
    for (int o = 16; o > 0; o >>= 1)
        ss += __shfl_xor_sync(0xffffffffu, ss, o);

    __shared__ float ws[8];
    if ((t & 31) == 0) ws[t >> 5] = ss;
    __syncthreads();
    float tot = ws[0]+ws[1]+ws[2]+ws[3]+ws[4]+ws[5]+ws[6]+ws[7];
    float rinv = rsqrtf(tot * (1.0f / DM) + 1e-6f);

    float4 cwv = *(const float4*)(g_cw + n * DM + t * 4);
    float o0 = v.x * cwv.x * rinv, o1 = v.y * cwv.y * rinv;
    float o2 = v.z * cwv.z * rinv, o3 = v.w * cwv.w * rinv;
    size_t base = (size_t)row * DM + t * 4;
    __half h0,l0,h1,l1,h2,l2,h3,l3;
    hsplit(o0,h0,l0); hsplit(o1,h1,l1); hsplit(o2,h2,l2); hsplit(o3,h3,l3);
    *(uint32_t*)(g_xnh + base)     = packh(h0, h1);
    *(uint32_t*)(g_xnh + base + 2) = packh(h2, h3);
    *(uint32_t*)(g_xnl + base)     = packh(l0, l1);
    *(uint32_t*)(g_xnl + base + 2) = packh(l2, l3);
}

// ---------------- mma GEMM: C[M,N] = (Ah+Al) @ (Bh+Bl), 3-term ----------------
// BM=128, BN=128, BK=32, 256 threads (8 warps, 4x2), cp.async double buffer.
#define GM_ASTRIDE 80
#define GM_BSTRIDE 272
#define GM_A_SZ (128 * GM_ASTRIDE)            // 10240 per array
#define GM_B_SZ (32 * GM_BSTRIDE)             // 8704
#define GM_BUF (2*GM_A_SZ + 2*GM_B_SZ)        // 37888
#define GEMM_SMEM (2 * GM_BUF)                // 75776

static __device__ __forceinline__ void gemm_load(uint32_t smb, int bufi,
    const __half* Ah, const __half* Al, const __half* Bh, const __half* Bl,
    int m0, int n0, int k0, int K, int N, int tid)
{
    uint32_t base = smb + bufi * GM_BUF;
    const int ar = tid >> 1, ac = (tid & 1) * 16;       // halves
    const __half* pah = Ah + (size_t)(m0 + ar) * K + k0 + ac;
    const __half* pal = Al + (size_t)(m0 + ar) * K + k0 + ac;
    cpasync16(base + ar*GM_ASTRIDE + ac*2,            pah);
    cpasync16(base + ar*GM_ASTRIDE + ac*2 + 16,       pah + 8);
    cpasync16(base + GM_A_SZ + ar*GM_ASTRIDE + ac*2,      pal);
    cpasync16(base + GM_A_SZ + ar*GM_ASTRIDE + ac*2 + 16, pal + 8);
    const int br = tid >> 3, bc = (tid & 7) * 16;       // halves
    const __half* pbh = Bh + (size_t)(k0 + br) * N + n0 + bc;
    const __half* pbl = Bl + (size_t)(k0 + br) * N + n0 + bc;
    uint32_t bb = base + 2 * GM_A_SZ;
    cpasync16(bb + br*GM_BSTRIDE + bc*2,      pbh);
    cpasync16(bb + br*GM_BSTRIDE + bc*2 + 16, pbh + 8);
    cpasync16(bb + GM_B_SZ + br*GM_BSTRIDE + bc*2,      pbl);
    cpasync16(bb + GM_B_SZ + br*GM_BSTRIDE + bc*2 + 16, pbl + 8);
}

__global__ __launch_bounds__(256) void mma_gemm_kernel(
    const __half* __restrict__ Ah, const __half* __restrict__ Al,
    const __half* __restrict__ Bh, const __half* __restrict__ Bl,
    float* __restrict__ C, int M, int N, int K)
{
    extern __shared__ char sm[];
    const uint32_t smb = smem_u32(sm);
    const int tid = threadIdx.x, lane = tid & 31, wid = tid >> 5;
    const int m0 = blockIdx.y * 128, n0 = blockIdx.x * 128;
    const int wm = (wid & 3) * 32, wn = (wid >> 2) * 64;

    float acc[2][8][4];
#pragma unroll
    for (int m = 0; m < 2; m++)
#pragma unroll
        for (int n = 0; n < 8; n++)
#pragma unroll
            for (int r = 0; r < 4; r++) acc[m][n][r] = 0.f;

    gemm_load(smb, 0, Ah, Al, Bh, Bl, m0, n0, 0, K, N, tid);
    CP_COMMIT();
    const int nk = K / 32;
    for (int s = 0; s < nk; s++) {
        if (s + 1 < nk)
            gemm_load(smb, (s + 1) & 1, Ah, Al, Bh, Bl, m0, n0, (s + 1) * 32, K, N, tid);
        CP_COMMIT();
        CP_WAIT1();
        __syncthreads();

        uint32_t base = smb + (s & 1) * GM_BUF;
        uint32_t a_h = base, a_l = base + GM_A_SZ;
        uint32_t b_h = base + 2 * GM_A_SZ, b_l = b_h + GM_B_SZ;
#pragma unroll
        for (int kt = 0; kt < 2; kt++) {
            uint32_t bfh[4][4], bfl[4][4];
            const uint32_t brow = kt * 16 + (lane & 7) + ((lane & 8) ? 8 : 0);
            const uint32_t bcol = wn * 2 + ((lane & 16) ? 16 : 0);
#pragma unroll
            for (int np = 0; np < 4; np++) {
                ldsm4t(bfh[np], b_h + brow * GM_BSTRIDE + bcol + np * 32);
                ldsm4t(bfl[np], b_l + brow * GM_BSTRIDE + bcol + np * 32);
            }
#pragma unroll
            for (int m = 0; m < 2; m++) {
                uint32_t afh[4], afl[4];
                const uint32_t arow = wm + m * 16 + (lane & 15);
                const uint32_t acol = kt * 32 + ((lane & 16) ? 16 : 0);
                ldsm4(afh, a_h + arow * GM_ASTRIDE + acol);
                ldsm4(afl, a_l + arow * GM_ASTRIDE + acol);
#pragma unroll
                for (int np = 0; np < 4; np++) {
                    mma_f16(acc[m][2*np],   afh, bfh[np]);
                    mma_f16(acc[m][2*np+1], afh, bfh[np] + 2);
                    mma_f16(acc[m][2*np],   afh, bfl[np]);
                    mma_f16(acc[m][2*np+1], afh, bfl[np] + 2);
                    mma_f16(acc[m][2*np],   afl, bfh[np]);
                    mma_f16(acc[m][2*np+1], afl, bfh[np] + 2);
                }
            }
        }
        __syncthreads();
    }

    const int g = lane >> 2, tg = lane & 3;
#pragma unroll
    for (int m = 0; m < 2; m++)
#pragma unroll
        for (int rr = 0; rr < 2; rr++) {
            int row = m0 + wm + m * 16 + g + rr * 8;
#pragma unroll
            for (int n = 0; n < 8; n++) {
                int col = n0 + wn + n * 8 + tg * 2;
                float2 v = make_float2(acc[m][n][rr*2], acc[m][n][rr*2+1]);
                *(float2*)(C + (size_t)row * N + col) = v;
            }
        }
}

// ---------------- kernel: qk rmsnorm + rope -> fp16 hi/lo Q,K,V ----------------
__global__ void qknorm_rope_kernel(const float* __restrict__ pos,
                                   const float* __restrict__ qk_scale)
{
    const int row  = blockIdx.x;
    const int n    = row / SEQL;
    const int l    = row % SEQL;
    const int warp = threadIdx.x >> 5;
    const int lane = threadIdx.x & 31;
    const int head = blockIdx.y * 4 + warp;

    const float* base = g_qkv + (size_t)row * (3 * DM);
    const int d1 = lane, d2 = lane + 32;

    float qa = base[head * DE + d1],          qb = base[head * DE + d2];
    float ka = base[DM + head * DE + d1],     kb = base[DM + head * DE + d2];
    float va = base[2 * DM + head * DE + d1], vb = base[2 * DM + head * DE + d2];

    float ssq = qa * qa + qb * qb;
    float ssk = ka * ka + kb * kb;
#pragma unroll
    for (int o = 16; o > 0; o >>= 1) {
        ssq += __shfl_xor_sync(0xffffffffu, ssq, o);
        ssk += __shfl_xor_sync(0xffffffffu, ssk, o);
    }

    float sc = expf(0.5f * fminf(qk_scale[head], 4.6051701860f) - 1.0397207708f);
    float rq = sc * rsqrtf(ssq * (1.0f / DE) + 1e-6f);
    float rk = sc * rsqrtf(ssk * (1.0f / DE) + 1e-6f);
    qa *= rq; qb *= rq; ka *= rk; kb *= rk;

    float pv = pos[(size_t)row * 2 + (lane >> 4)];
    int   j  = lane & 15;
    float fr = expf(1.14472988584940017f + (float)(j * 16 + head) * (2.30258509299404568f / 256.0f));
    float th = pv * fr;
    float cth = cosf(th), sth = sinf(th);

    float qo1 = qa * cth - qb * sth, qo2 = qb * cth + qa * sth;
    float ko1 = ka * cth - kb * sth, ko2 = kb * cth + ka * sth;

    size_t ob = ((size_t)(n * NH + head) * SEQL + l) * DE;
    __half h, lo;
    hsplit(qo1, h, lo); g_qh[ob + d1] = h; g_ql[ob + d1] = lo;
    hsplit(qo2, h, lo); g_qh[ob + d2] = h; g_ql[ob + d2] = lo;
    hsplit(ko1, h, lo); g_kh[ob + d1] = h; g_kl[ob + d1] = lo;
    hsplit(ko2, h, lo); g_kh[ob + d2] = h; g_kl[ob + d2] = lo;
    hsplit(va,  h, lo); g_vh[ob + d1] = h; g_vl[ob + d1] = lo;
    hsplit(vb,  h, lo); g_vh[ob + d2] = h; g_vl[ob + d2] = lo;
}

// ---------------- attention via mma.sync ----------------
// CTA: 128 q-rows x (head,batch), 4 warps (32 q each), TK=64 keys/tile, 32 tiles.
#define AT_STRIDE 144
#define AT_QH 0
#define AT_QL (128 * AT_STRIDE)               // 18432
#define AT_KV0 (2 * 128 * AT_STRIDE)          // 36864
#define AT_ARR (64 * AT_STRIDE)               // 9216 per array
#define AT_BUF (4 * AT_ARR)                   // 36864 (Kh,Kl,Vh,Vl)
#define ATTN_SMEM (AT_KV0 + 2 * AT_BUF)       // 110592

static __device__ __forceinline__ void attn_load_kv(uint32_t smb, size_t bh,
                                                    int tid, int t, int bufi)
{
    const int k0 = t * 64;
    const int r  = tid >> 1;
    const int hc = (tid & 1) * 32;           // halves offset 0/32
    uint32_t base = smb + AT_KV0 + bufi * AT_BUF + r * AT_STRIDE + hc * 2;
    const __half* s0 = g_kh + (bh + k0 + r) * DE + hc;
    const __half* s1 = g_kl + (bh + k0 + r) * DE + hc;
    const __half* s2 = g_vh + (bh + k0 + r) * DE + hc;
    const __half* s3 = g_vl + (bh + k0 + r) * DE + hc;
#pragma unroll
    for (int c = 0; c < 4; c++) {
        cpasync16(base + 0*AT_ARR + c*16, s0 + c*8);
        cpasync16(base + 1*AT_ARR + c*16, s1 + c*8);
        cpasync16(base + 2*AT_ARR + c*16, s2 + c*8);
        cpasync16(base + 3*AT_ARR + c*16, s3 + c*8);
    }
}

__global__ __launch_bounds__(128) void attn_mma_kernel()
{
    extern __shared__ char sm[];
    const uint32_t smb = smem_u32(sm);
    const int tid = threadIdx.x, lane = tid & 31, wid = tid >> 5;
    const int q0 = blockIdx.x * 128, head = blockIdx.y, b = blockIdx.z;
    const size_t bh = (size_t)(b * NH + head) * SEQL;
    const float SCL2 = 0.18033688011112042f;   // log2(e)/8

    // Q -> smem (hi/lo), row = tid
    {
        const __half* qh = g_qh + (bh + q0 + tid) * DE;
        const __half* ql = g_ql + (bh + q0 + tid) * DE;
        uint32_t dh = smb + AT_QH + tid * AT_STRIDE;
        uint32_t dl = smb + AT_QL + tid * AT_STRIDE;
#pragma unroll
        for (int c = 0; c < 8; c++) {
            cpasync16(dh + c*16, qh + c*8);
            cpasync16(dl + c*16, ql + c*8);
        }
    }
    attn_load_kv(smb, bh, tid, 0, 0);
    CP_COMMIT();

    float O[2][8][4];
#pragma unroll
    for (int m = 0; m < 2; m++)
#pragma unroll
        for (int n = 0; n < 8; n++)
#pragma unroll
            for (int r = 0; r < 4; r++) O[m][n][r] = 0.f;
    float ls[2][2] = {{0.f, 0.f}, {0.f, 0.f}};

    for (int t = 0; t < SEQL / 64; t++) {
        if (t + 1 < SEQL / 64) attn_load_kv(smb, bh, tid, t + 1, (t + 1) & 1);
        CP_COMMIT();
        CP_WAIT1();
        __syncthreads();

        uint32_t kb  = smb + AT_KV0 + (t & 1) * AT_BUF;
        uint32_t kh_b = kb, kl_b = kb + AT_ARR;
        uint32_t vh_b = kb + 2*AT_ARR, vl_b = kb + 3*AT_ARR;

        float S[2][8][4];
#pragma unroll
        for (int m = 0; m < 2; m++)
#pragma unroll
            for (int n = 0; n < 8; n++)
#pragma unroll
                for (int r = 0; r < 4; r++) S[m][n][r] = 0.f;

        // ---- S = Q K^T ----
#pragma unroll
        for (int kt = 0; kt < 4; kt++) {
            uint32_t kfh[4][4], kfl[4][4];
            const uint32_t krow = (lane & 7) + ((lane & 16) ? 8 : 0);
            const uint32_t kcol = kt * 32 + ((lane & 8) ? 16 : 0);
#pragma unroll
            for (int np = 0; np < 4; np++) {
                ldsm4(kfh[np], kh_b + (np*16 + krow) * AT_STRIDE + kcol);
                ldsm4(kfl[np], kl_b + (np*16 + krow) * AT_STRIDE + kcol);
            }
#pragma unroll
            for (int m = 0; m < 2; m++) {
                uint32_t qah[4], qal[4];
                const uint32_t qrow = wid*32 + m*16 + (lane & 15);
                const uint32_t qcol = kt * 32 + ((lane & 16) ? 16 : 0);
                ldsm4(qah, smb + AT_QH + qrow * AT_STRIDE + qcol);
                ldsm4(qal, smb + AT_QL + qrow * AT_STRIDE + qcol);
#pragma unroll
                for (int np = 0; np < 4; np++) {
                    mma_f16(S[m][2*np],   qah, kfh[np]);
                    mma_f16(S[m][2*np+1], qah, kfh[np] + 2);
                    mma_f16(S[m][2*np],   qah, kfl[np]);
                    mma_f16(S[m][2*np+1], qah, kfl[np] + 2);
                    mma_f16(S[m][2*np],   qal, kfh[np]);
                    mma_f16(S[m][2*np+1], qal, kfh[np] + 2);
                }
            }
        }

        // ---- P = exp(S/8), convert to A-fragments (reg-to-reg) ----
        uint32_t pah[2][4][4], pal[2][4][4];
#pragma unroll
        for (int m = 0; m < 2; m++)
#pragma unroll
            for (int n = 0; n < 8; n++) {
                float p0 = fast_exp2(S[m][n][0] * SCL2);
                float p1 = fast_exp2(S[m][n][1] * SCL2);
                float p2 = fast_exp2(S[m][n][2] * SCL2);
                float p3 = fast_exp2(S[m][n][3] * SCL2);
                ls[m][0] += p0 + p1;
                ls[m][1] += p2 + p3;
                __half h0,l0,h1,l1,h2,l2,h3,l3;
                hsplit(p0,h0,l0); hsplit(p1,h1,l1);
                hsplit(p2,h2,l2); hsplit(p3,h3,l3);
                const int kt = n >> 1, rb = (n & 1) * 2;
                pah[m][kt][rb]     = packh(h0, h1);
                pah[m][kt][rb + 1] = packh(h2, h3);
                pal[m][kt][rb]     = packh(l0, l1);
                pal[m][kt][rb + 1] = packh(l2, l3);
            }

        // ---- O += P V ----
#pragma unroll
        for (int kt = 0; kt < 4; kt++) {
            uint32_t vfh[4][4], vfl[4][4];
            const uint32_t vrow = kt*16 + (lane & 7) + ((lane & 8) ? 8 : 0);
            const uint32_t vcol = ((lane & 16) ? 16 : 0);
#pragma unroll
            for (int np = 0; np < 4; np++) {
                ldsm4t(vfh[np], vh_b + vrow * AT_STRIDE + np*32 + vcol);
                ldsm4t(vfl[np], vl_b + vrow * AT_STRIDE + np*32 + vcol);
            }
#pragma unroll
            for (int m = 0; m < 2; m++)
#pragma unroll
                for (int np = 0; np < 4; np++) {
                    mma_f16(O[m][2*np],   pah[m][kt], vfh[np]);
                    mma_f16(O[m][2*np+1], pah[m][kt], vfh[np] + 2);
                    mma_f16(O[m][2*np],   pah[m][kt], vfl[np]);
                    mma_f16(O[m][2*np+1], pah[m][kt], vfl[np] + 2);
                    mma_f16(O[m][2*np],   pal[m][kt], vfh[np]);
                    mma_f16(O[m][2*np+1], pal[m][kt], vfh[np] + 2);
                }
        }
        __syncthreads();
    }

    // ---- epilogue ----
#pragma unroll
    for (int m = 0; m < 2; m++)
#pragma unroll
        for (int r = 0; r < 2; r++) {
            ls[m][r] += __shfl_xor_sync(0xffffffffu, ls[m][r], 1);
            ls[m][r] += __shfl_xor_sync(0xffffffffu, ls[m][r], 2);
        }
    const int g = lane >> 2, tg = lane & 3;
#pragma unroll
    for (int m = 0; m < 2; m++) {
#pragma unroll
        for (int rr = 0; rr < 2; rr++) {
            const int row = q0 + wid*32 + m*16 + g + rr*8;
            const float inv = 1.0f / ls[m][rr];
            const size_t rb = ((size_t)b * SEQL + row) * DM + head * DE;
#pragma unroll
            for (int n = 0; n < 8; n++) {
                float o0 = O[m][n][rr*2]   * inv;
                float o1 = O[m][n][rr*2+1] * inv;
                __half h0,l0,h1,l1;
                hsplit(o0,h0,l0); hsplit(o1,h1,l1);
                const int col = n*8 + tg*2;
                *(uint32_t*)(g_oh + rb + col) = packh(h0, h1);
                *(uint32_t*)(g_ol + rb + col) = packh(l0, l1);
            }
        }
    }
}

// ---------------- launch ----------------
extern "C" void kernel_launch(void* const* d_in, const int* in_sizes, int n_in,
                              void* d_out, int out_size)
{
    const float* x        = (const float*)d_in[0];
    const float* pos      = (const float*)d_in[1];
    const float* cond     = (const float*)d_in[2];
    const float* w_cond   = (const float*)d_in[3];
    const float* w_qkv    = (const float*)d_in[4];
    const float* qk_scale = (const float*)d_in[5];
    const float* w_out    = (const float*)d_in[6];
    float* out = (float*)d_out;

    float *p_qkv;
    __half *p_xnh, *p_xnl, *p_oh, *p_ol, *p_wqh, *p_wql, *p_woh, *p_wol;
    cudaGetSymbolAddress((void**)&p_qkv, g_qkv);
    cudaGetSymbolAddress((void**)&p_xnh, g_xnh);
    cudaGetSymbolAddress((void**)&p_xnl, g_xnl);
    cudaGetSymbolAddress((void**)&p_oh,  g_oh);
    cudaGetSymbolAddress((void**)&p_ol,  g_ol);
    cudaGetSymbolAddress((void**)&p_wqh, g_wqh);
    cudaGetSymbolAddress((void**)&p_wql, g_wql);
    cudaGetSymbolAddress((void**)&p_woh, g_woh);
    cudaGetSymbolAddress((void**)&p_wol, g_wol);

    static int s_attr = 0;
    if (!s_attr) {
        cudaFuncSetAttribute(attn_mma_kernel,
                             cudaFuncAttributeMaxDynamicSharedMemorySize, ATTN_SMEM);
        cudaFuncSetAttribute(mma_gemm_kernel,
                             cudaFuncAttributeMaxDynamicSharedMemorySize, GEMM_SMEM);
        s_attr = 1;
    }

    split_kernel<<<(DM*3*DM + 255)/256, 256>>>(w_qkv, p_wqh, p_wql, DM*3*DM);
    split_kernel<<<(DM*DM + 255)/256, 256>>>(w_out, p_woh, p_wol, DM*DM);
    cond_gemm_kernel<<<dim3(DM/256, NB), 256>>>(cond, w_cond);
    rmsnorm_x_kernel<<<ROWS, 256>>>(x);
    mma_gemm_kernel<<<dim3(3*DM/128, ROWS/128), 256, GEMM_SMEM>>>(
        p_xnh, p_xnl, p_wqh, p_wql, p_qkv, ROWS, 3*DM, DM);
    qknorm_rope_kernel<<<dim3(ROWS, NH/4), 128>>>(pos, qk_scale);
    attn_mma_kernel<<<dim3(SEQL/128, NH, NB), 128, ATTN_SMEM>>>();
    mma_gemm_kernel<<<dim3(DM/128, ROWS/128), 256, GEMM_SMEM>>>(
        p_oh, p_ol, p_woh, p_wol, out, ROWS, DM, DM);
}

// round 4
// speedup vs baseline: 2.8982x; 1.1601x over previous
#include <cuda_runtime.h>
#include <cuda_fp16.h>
#include <math.h>
#include <stdint.h>

// Problem shape: n=2, l=2048, d_model=1024, h=16, e=64
#define NB 2
#define SEQL 2048
#define DM 1024
#define NH 16
#define DE 64
#define ROWS (NB * SEQL)          // 4096

// ---------------- scratch ----------------
__device__ float  g_cw[NB * DM];
__device__ float  g_qkv[ROWS * 3 * DM];
__device__ __half g_xnh[ROWS * DM], g_xnl[ROWS * DM];
__device__ __half g_qh[NB*NH*SEQL*DE];
__device__ __half g_kh[NB*NH*SEQL*DE], g_kl[NB*NH*SEQL*DE];
__device__ __half g_vh[NB*NH*SEQL*DE], g_vl[NB*NH*SEQL*DE];
__device__ __half g_oh[ROWS * DM], g_ol[ROWS * DM];
__device__ __half g_wqh[DM * 3 * DM], g_wql[DM * 3 * DM];
__device__ __half g_woh[DM * DM],     g_wol[DM * DM];

// ---------------- helpers ----------------
static __device__ __forceinline__ uint32_t smem_u32(const void* p) {
    uint32_t a;
    asm("{ .reg .u64 t; cvta.to.shared.u64 t, %1; cvt.u32.u64 %0, t; }" : "=r"(a) : "l"(p));
    return a;
}
static __device__ __forceinline__ void cpasync16(uint32_t dst, const void* src) {
    asm volatile("cp.async.cg.shared.global [%0], [%1], 16;" :: "r"(dst), "l"(src));
}
#define CP_COMMIT() asm volatile("cp.async.commit_group;" ::: "memory")
#define CP_WAIT1()  asm volatile("cp.async.wait_group 1;"  ::: "memory")
static __device__ __forceinline__ void ldsm4(uint32_t* r, uint32_t a) {
    asm volatile("ldmatrix.sync.aligned.m8n8.x4.shared.b16 {%0,%1,%2,%3}, [%4];"
        : "=r"(r[0]), "=r"(r[1]), "=r"(r[2]), "=r"(r[3]) : "r"(a));
}
static __device__ __forceinline__ void ldsm4t(uint32_t* r, uint32_t a) {
    asm volatile("ldmatrix.sync.aligned.m8n8.x4.trans.shared.b16 {%0,%1,%2,%3}, [%4];"
        : "=r"(r[0]), "=r"(r[1]), "=r"(r[2]), "=r"(r[3]) : "r"(a));
}
static __device__ __forceinline__ void mma_f16(float* c, const uint32_t* a, const uint32_t* b) {
    asm volatile("mma.sync.aligned.m16n8k16.row.col.f32.f16.f16.f32 "
        "{%0,%1,%2,%3}, {%4,%5,%6,%7}, {%8,%9}, {%0,%1,%2,%3};"
        : "+f"(c[0]), "+f"(c[1]), "+f"(c[2]), "+f"(c[3])
        : "r"(a[0]), "r"(a[1]), "r"(a[2]), "r"(a[3]), "r"(b[0]), "r"(b[1]));
}
static __device__ __forceinline__ float fast_exp2(float x) {
    float y; asm("ex2.approx.f32 %0, %1;" : "=f"(y) : "f"(x)); return y;
}
static __device__ __forceinline__ void hsplit(float x, __half& h, __half& l) {
    h = __float2half_rn(x);
    l = __float2half_rn(x - __half2float(h));
}
static __device__ __forceinline__ uint32_t packh(__half a, __half b) {
    return (uint32_t)__half_as_ushort(a) | ((uint32_t)__half_as_ushort(b) << 16);
}

// ---------------- kernel: split fp32 -> fp16 hi/lo ----------------
__global__ void split_kernel(const float* __restrict__ s, __half* __restrict__ h,
                             __half* __restrict__ l, int n)
{
    int i = blockIdx.x * blockDim.x + threadIdx.x;
    if (i < n) {
        float v = s[i];
        __half hh = __float2half_rn(v);
        h[i] = hh;
        l[i] = __float2half_rn(v - __half2float(hh));
    }
}

// ---------------- kernel 1: cw = cond @ w_cond + 1 ----------------
__global__ void cond_gemm_kernel(const float* __restrict__ cond,
                                 const float* __restrict__ w_cond)
{
    __shared__ float cs[DM];
    const int n = blockIdx.y;
    for (int k = threadIdx.x; k < DM; k += blockDim.x)
        cs[k] = cond[n * DM + k];
    __syncthreads();
    const int j = blockIdx.x * blockDim.x + threadIdx.x;
    float acc = 0.f;
#pragma unroll 8
    for (int k = 0; k < DM; k++)
        acc = fmaf(cs[k], w_cond[k * DM + j], acc);
    g_cw[n * DM + j] = acc + 1.0f;
}

// ---------------- kernel 2: xn = rms_norm(x, cw) -> fp16 hi/lo ----------------
__global__ void rmsnorm_x_kernel(const float* __restrict__ x)
{
    const int row = blockIdx.x;
    const int n = row / SEQL;
    const int t = threadIdx.x;

    float4 v = *(const float4*)(x + (size_t)row * DM + t * 4);
    float ss = v.x * v.x + v.y * v.y + v.z * v.z + v.w * v.w;
#pragma unroll
    for (int o = 16; o > 0; o >>= 1)
        ss += __shfl_xor_sync(0xffffffffu, ss, o);

    __shared__ float ws[8];
    if ((t & 31) == 0) ws[t >> 5] = ss;
    __syncthreads();
    float tot = ws[0]+ws[1]+ws[2]+ws[3]+ws[4]+ws[5]+ws[6]+ws[7];
    float rinv = rsqrtf(tot * (1.0f / DM) + 1e-6f);

    float4 cwv = *(const float4*)(g_cw + n * DM + t * 4);
    float o0 = v.x * cwv.x * rinv, o1 = v.y * cwv.y * rinv;
    float o2 = v.z * cwv.z * rinv, o3 = v.w * cwv.w * rinv;
    size_t base = (size_t)row * DM + t * 4;
    __half h0,l0,h1,l1,h2,l2,h3,l3;
    hsplit(o0,h0,l0); hsplit(o1,h1,l1); hsplit(o2,h2,l2); hsplit(o3,h3,l3);
    *(uint32_t*)(g_xnh + base)     = packh(h0, h1);
    *(uint32_t*)(g_xnh + base + 2) = packh(h2, h3);
    *(uint32_t*)(g_xnl + base)     = packh(l0, l1);
    *(uint32_t*)(g_xnl + base + 2) = packh(l2, l3);
}

// ---------------- mma GEMM: C[M,N] = (Ah+Al) @ (Bh+Bl), 3-term ----------------
// BM=128, BN=128, BK=32, 256 threads (8 warps, 4x2), cp.async double buffer.
#define GM_ASTRIDE 80
#define GM_BSTRIDE 272
#define GM_A_SZ (128 * GM_ASTRIDE)            // 10240 per array
#define GM_B_SZ (32 * GM_BSTRIDE)             // 8704
#define GM_BUF (2*GM_A_SZ + 2*GM_B_SZ)        // 37888
#define GEMM_SMEM (2 * GM_BUF)                // 75776

static __device__ __forceinline__ void gemm_load(uint32_t smb, int bufi,
    const __half* Ah, const __half* Al, const __half* Bh, const __half* Bl,
    int m0, int n0, int k0, int K, int N, int tid)
{
    uint32_t base = smb + bufi * GM_BUF;
    const int ar = tid >> 1, ac = (tid & 1) * 16;       // halves
    const __half* pah = Ah + (size_t)(m0 + ar) * K + k0 + ac;
    const __half* pal = Al + (size_t)(m0 + ar) * K + k0 + ac;
    cpasync16(base + ar*GM_ASTRIDE + ac*2,            pah);
    cpasync16(base + ar*GM_ASTRIDE + ac*2 + 16,       pah + 8);
    cpasync16(base + GM_A_SZ + ar*GM_ASTRIDE + ac*2,      pal);
    cpasync16(base + GM_A_SZ + ar*GM_ASTRIDE + ac*2 + 16, pal + 8);
    const int br = tid >> 3, bc = (tid & 7) * 16;       // halves
    const __half* pbh = Bh + (size_t)(k0 + br) * N + n0 + bc;
    const __half* pbl = Bl + (size_t)(k0 + br) * N + n0 + bc;
    uint32_t bb = base + 2 * GM_A_SZ;
    cpasync16(bb + br*GM_BSTRIDE + bc*2,      pbh);
    cpasync16(bb + br*GM_BSTRIDE + bc*2 + 16, pbh + 8);
    cpasync16(bb + GM_B_SZ + br*GM_BSTRIDE + bc*2,      pbl);
    cpasync16(bb + GM_B_SZ + br*GM_BSTRIDE + bc*2 + 16, pbl + 8);
}

__global__ __launch_bounds__(256) void mma_gemm_kernel(
    const __half* __restrict__ Ah, const __half* __restrict__ Al,
    const __half* __restrict__ Bh, const __half* __restrict__ Bl,
    float* __restrict__ C, int M, int N, int K)
{
    extern __shared__ char sm[];
    const uint32_t smb = smem_u32(sm);
    const int tid = threadIdx.x, lane = tid & 31, wid = tid >> 5;
    const int m0 = blockIdx.y * 128, n0 = blockIdx.x * 128;
    const int wm = (wid & 3) * 32, wn = (wid >> 2) * 64;

    float acc[2][8][4];
#pragma unroll
    for (int m = 0; m < 2; m++)
#pragma unroll
        for (int n = 0; n < 8; n++)
#pragma unroll
            for (int r = 0; r < 4; r++) acc[m][n][r] = 0.f;

    gemm_load(smb, 0, Ah, Al, Bh, Bl, m0, n0, 0, K, N, tid);
    CP_COMMIT();
    const int nk = K / 32;
    for (int s = 0; s < nk; s++) {
        if (s + 1 < nk)
            gemm_load(smb, (s + 1) & 1, Ah, Al, Bh, Bl, m0, n0, (s + 1) * 32, K, N, tid);
        CP_COMMIT();
        CP_WAIT1();
        __syncthreads();

        uint32_t base = smb + (s & 1) * GM_BUF;
        uint32_t a_h = base, a_l = base + GM_A_SZ;
        uint32_t b_h = base + 2 * GM_A_SZ, b_l = b_h + GM_B_SZ;
#pragma unroll
        for (int kt = 0; kt < 2; kt++) {
            uint32_t bfh[4][4], bfl[4][4];
            const uint32_t brow = kt * 16 + (lane & 7) + ((lane & 8) ? 8 : 0);
            const uint32_t bcol = wn * 2 + ((lane & 16) ? 16 : 0);
#pragma unroll
            for (int np = 0; np < 4; np++) {
                ldsm4t(bfh[np], b_h + brow * GM_BSTRIDE + bcol + np * 32);
                ldsm4t(bfl[np], b_l + brow * GM_BSTRIDE + bcol + np * 32);
            }
#pragma unroll
            for (int m = 0; m < 2; m++) {
                uint32_t afh[4], afl[4];
                const uint32_t arow = wm + m * 16 + (lane & 15);
                const uint32_t acol = kt * 32 + ((lane & 16) ? 16 : 0);
                ldsm4(afh, a_h + arow * GM_ASTRIDE + acol);
                ldsm4(afl, a_l + arow * GM_ASTRIDE + acol);
#pragma unroll
                for (int np = 0; np < 4; np++) {
                    mma_f16(acc[m][2*np],   afh, bfh[np]);
                    mma_f16(acc[m][2*np+1], afh, bfh[np] + 2);
                    mma_f16(acc[m][2*np],   afh, bfl[np]);
                    mma_f16(acc[m][2*np+1], afh, bfl[np] + 2);
                    mma_f16(acc[m][2*np],   afl, bfh[np]);
                    mma_f16(acc[m][2*np+1], afl, bfh[np] + 2);
                }
            }
        }
        __syncthreads();
    }

    const int g = lane >> 2, tg = lane & 3;
#pragma unroll
    for (int m = 0; m < 2; m++)
#pragma unroll
        for (int rr = 0; rr < 2; rr++) {
            int row = m0 + wm + m * 16 + g + rr * 8;
#pragma unroll
            for (int n = 0; n < 8; n++) {
                int col = n0 + wn + n * 8 + tg * 2;
                float2 v = make_float2(acc[m][n][rr*2], acc[m][n][rr*2+1]);
                *(float2*)(C + (size_t)row * N + col) = v;
            }
        }
}

// ---------------- kernel: qk rmsnorm + rope -> fp16 hi/lo Q,K,V ----------------
__global__ void qknorm_rope_kernel(const float* __restrict__ pos,
                                   const float* __restrict__ qk_scale)
{
    const int row  = blockIdx.x;
    const int n    = row / SEQL;
    const int l    = row % SEQL;
    const int warp = threadIdx.x >> 5;
    const int lane = threadIdx.x & 31;
    const int head = blockIdx.y * 4 + warp;

    const float* base = g_qkv + (size_t)row * (3 * DM);
    const int d1 = lane, d2 = lane + 32;

    float qa = base[head * DE + d1],          qb = base[head * DE + d2];
    float ka = base[DM + head * DE + d1],     kb = base[DM + head * DE + d2];
    float va = base[2 * DM + head * DE + d1], vb = base[2 * DM + head * DE + d2];

    float ssq = qa * qa + qb * qb;
    float ssk = ka * ka + kb * kb;
#pragma unroll
    for (int o = 16; o > 0; o >>= 1) {
        ssq += __shfl_xor_sync(0xffffffffu, ssq, o);
        ssk += __shfl_xor_sync(0xffffffffu, ssk, o);
    }

    float sc = expf(0.5f * fminf(qk_scale[head], 4.6051701860f) - 1.0397207708f);
    float rq = sc * rsqrtf(ssq * (1.0f / DE) + 1e-6f);
    float rk = sc * rsqrtf(ssk * (1.0f / DE) + 1e-6f);
    qa *= rq; qb *= rq; ka *= rk; kb *= rk;

    float pv = pos[(size_t)row * 2 + (lane >> 4)];
    int   j  = lane & 15;
    float fr = expf(1.14472988584940017f + (float)(j * 16 + head) * (2.30258509299404568f / 256.0f));
    float th = pv * fr;
    float cth = cosf(th), sth = sinf(th);

    float qo1 = qa * cth - qb * sth, qo2 = qb * cth + qa * sth;
    float ko1 = ka * cth - kb * sth, ko2 = kb * cth + ka * sth;

    size_t ob = ((size_t)(n * NH + head) * SEQL + l) * DE;
    __half h, lo;
    // Q: hi only (2-term S drops Qlo)
    g_qh[ob + d1] = __float2half_rn(qo1);
    g_qh[ob + d2] = __float2half_rn(qo2);
    hsplit(ko1, h, lo); g_kh[ob + d1] = h; g_kl[ob + d1] = lo;
    hsplit(ko2, h, lo); g_kh[ob + d2] = h; g_kl[ob + d2] = lo;
    hsplit(va,  h, lo); g_vh[ob + d1] = h; g_vl[ob + d1] = lo;
    hsplit(vb,  h, lo); g_vh[ob + d2] = h; g_vl[ob + d2] = lo;
}

// ---------------- attention via mma.sync (2-term S, 2-term PV) ----------------
// CTA: 128 q-rows x (head,batch), 4 warps (32 q each), TK=64 keys/tile, 32 tiles.
#define AT_STRIDE 144
#define AT_QH 0
#define AT_KV0 (128 * AT_STRIDE)              // 18432
#define AT_ARR (64 * AT_STRIDE)               // 9216 per array
#define AT_BUF (4 * AT_ARR)                   // 36864 (Kh,Kl,Vh,Vl)
#define ATTN_SMEM (AT_KV0 + 2 * AT_BUF)       // 92160

static __device__ __forceinline__ void attn_load_kv(uint32_t smb, size_t bh,
                                                    int tid, int t, int bufi)
{
    const int k0 = t * 64;
    const int r  = tid >> 1;
    const int hc = (tid & 1) * 32;           // halves offset 0/32
    uint32_t base = smb + AT_KV0 + bufi * AT_BUF + r * AT_STRIDE + hc * 2;
    const __half* s0 = g_kh + (bh + k0 + r) * DE + hc;
    const __half* s1 = g_kl + (bh + k0 + r) * DE + hc;
    const __half* s2 = g_vh + (bh + k0 + r) * DE + hc;
    const __half* s3 = g_vl + (bh + k0 + r) * DE + hc;
#pragma unroll
    for (int c = 0; c < 4; c++) {
        cpasync16(base + 0*AT_ARR + c*16, s0 + c*8);
        cpasync16(base + 1*AT_ARR + c*16, s1 + c*8);
        cpasync16(base + 2*AT_ARR + c*16, s2 + c*8);
        cpasync16(base + 3*AT_ARR + c*16, s3 + c*8);
    }
}

__global__ __launch_bounds__(128) void attn_mma_kernel()
{
    extern __shared__ char sm[];
    const uint32_t smb = smem_u32(sm);
    const int tid = threadIdx.x, lane = tid & 31, wid = tid >> 5;
    const int q0 = blockIdx.x * 128, head = blockIdx.y, b = blockIdx.z;
    const size_t bh = (size_t)(b * NH + head) * SEQL;
    const float SCL2 = 0.18033688011112042f;   // log2(e)/8

    // Q hi -> smem, row = tid (own commit group so we can wait on it first)
    {
        const __half* qh = g_qh + (bh + q0 + tid) * DE;
        uint32_t dh = smb + AT_QH + tid * AT_STRIDE;
#pragma unroll
        for (int c = 0; c < 8; c++)
            cpasync16(dh + c*16, qh + c*8);
    }
    CP_COMMIT();
    attn_load_kv(smb, bh, tid, 0, 0);
    CP_COMMIT();
    CP_WAIT1();                 // Q group done
    __syncthreads();

    // hoist Q fragments (invariant across the whole K loop)
    uint32_t qfr[2][4][4];
#pragma unroll
    for (int m = 0; m < 2; m++)
#pragma unroll
        for (int kt = 0; kt < 4; kt++) {
            const uint32_t qrow = wid*32 + m*16 + (lane & 15);
            const uint32_t qcol = kt * 32 + ((lane & 16) ? 16 : 0);
            ldsm4(qfr[m][kt], smb + AT_QH + qrow * AT_STRIDE + qcol);
        }

    float O[2][8][4];
#pragma unroll
    for (int m = 0; m < 2; m++)
#pragma unroll
        for (int n = 0; n < 8; n++)
#pragma unroll
            for (int r = 0; r < 4; r++) O[m][n][r] = 0.f;
    float ls[2][2] = {{0.f, 0.f}, {0.f, 0.f}};

    for (int t = 0; t < SEQL / 64; t++) {
        if (t + 1 < SEQL / 64) attn_load_kv(smb, bh, tid, t + 1, (t + 1) & 1);
        CP_COMMIT();
        CP_WAIT1();
        __syncthreads();

        uint32_t kb  = smb + AT_KV0 + (t & 1) * AT_BUF;
        uint32_t kh_b = kb, kl_b = kb + AT_ARR;
        uint32_t vh_b = kb + 2*AT_ARR, vl_b = kb + 3*AT_ARR;

        float S[2][8][4];
#pragma unroll
        for (int m = 0; m < 2; m++)
#pragma unroll
            for (int n = 0; n < 8; n++)
#pragma unroll
                for (int r = 0; r < 4; r++) S[m][n][r] = 0.f;

        // ---- S = Qh (Kh + Kl)^T ----
#pragma unroll
        for (int kt = 0; kt < 4; kt++) {
            uint32_t kfh[4][4], kfl[4][4];
            const uint32_t krow = (lane & 7) + ((lane & 16) ? 8 : 0);
            const uint32_t kcol = kt * 32 + ((lane & 8) ? 16 : 0);
#pragma unroll
            for (int np = 0; np < 4; np++) {
                ldsm4(kfh[np], kh_b + (np*16 + krow) * AT_STRIDE + kcol);
                ldsm4(kfl[np], kl_b + (np*16 + krow) * AT_STRIDE + kcol);
            }
#pragma unroll
            for (int m = 0; m < 2; m++)
#pragma unroll
                for (int np = 0; np < 4; np++) {
                    mma_f16(S[m][2*np],   qfr[m][kt], kfh[np]);
                    mma_f16(S[m][2*np+1], qfr[m][kt], kfh[np] + 2);
                    mma_f16(S[m][2*np],   qfr[m][kt], kfl[np]);
                    mma_f16(S[m][2*np+1], qfr[m][kt], kfl[np] + 2);
                }
        }

        // ---- P = exp(S/8) -> fp16 hi only, A-fragments (reg-to-reg) ----
        uint32_t pa[2][4][4];
#pragma unroll
        for (int m = 0; m < 2; m++)
#pragma unroll
            for (int n = 0; n < 8; n++) {
                float p0 = fast_exp2(S[m][n][0] * SCL2);
                float p1 = fast_exp2(S[m][n][1] * SCL2);
                float p2 = fast_exp2(S[m][n][2] * SCL2);
                float p3 = fast_exp2(S[m][n][3] * SCL2);
                ls[m][0] += p0 + p1;
                ls[m][1] += p2 + p3;
                const int kt = n >> 1, rb = (n & 1) * 2;
                pa[m][kt][rb]     = packh(__float2half_rn(p0), __float2half_rn(p1));
                pa[m][kt][rb + 1] = packh(__float2half_rn(p2), __float2half_rn(p3));
            }

        // ---- O += Ph (Vh + Vl) ----
#pragma unroll
        for (int kt = 0; kt < 4; kt++) {
            uint32_t vfh[4][4], vfl[4][4];
            const uint32_t vrow = kt*16 + (lane & 7) + ((lane & 8) ? 8 : 0);
            const uint32_t vcol = ((lane & 16) ? 16 : 0);
#pragma unroll
            for (int np = 0; np < 4; np++) {
                ldsm4t(vfh[np], vh_b + vrow * AT_STRIDE + np*32 + vcol);
                ldsm4t(vfl[np], vl_b + vrow * AT_STRIDE + np*32 + vcol);
            }
#pragma unroll
            for (int m = 0; m < 2; m++)
#pragma unroll
                for (int np = 0; np < 4; np++) {
                    mma_f16(O[m][2*np],   pa[m][kt], vfh[np]);
                    mma_f16(O[m][2*np+1], pa[m][kt], vfh[np] + 2);
                    mma_f16(O[m][2*np],   pa[m][kt], vfl[np]);
                    mma_f16(O[m][2*np+1], pa[m][kt], vfl[np] + 2);
                }
        }
        __syncthreads();
    }

    // ---- epilogue ----
#pragma unroll
    for (int m = 0; m < 2; m++)
#pragma unroll
        for (int r = 0; r < 2; r++) {
            ls[m][r] += __shfl_xor_sync(0xffffffffu, ls[m][r], 1);
            ls[m][r] += __shfl_xor_sync(0xffffffffu, ls[m][r], 2);
        }
    const int g = lane >> 2, tg = lane & 3;
#pragma unroll
    for (int m = 0; m < 2; m++) {
#pragma unroll
        for (int rr = 0; rr < 2; rr++) {
            const int row = q0 + wid*32 + m*16 + g + rr*8;
            const float inv = 1.0f / ls[m][rr];
            const size_t rb = ((size_t)b * SEQL + row) * DM + head * DE;
#pragma unroll
            for (int n = 0; n < 8; n++) {
                float o0 = O[m][n][rr*2]   * inv;
                float o1 = O[m][n][rr*2+1] * inv;
                __half h0,l0,h1,l1;
                hsplit(o0,h0,l0); hsplit(o1,h1,l1);
                const int col = n*8 + tg*2;
                *(uint32_t*)(g_oh + rb + col) = packh(h0, h1);
                *(uint32_t*)(g_ol + rb + col) = packh(l0, l1);
            }
        }
    }
}

// ---------------- launch ----------------
extern "C" void kernel_launch(void* const* d_in, const int* in_sizes, int n_in,
                              void* d_out, int out_size)
{
    const float* x        = (const float*)d_in[0];
    const float* pos      = (const float*)d_in[1];
    const float* cond     = (const float*)d_in[2];
    const float* w_cond   = (const float*)d_in[3];
    const float* w_qkv    = (const float*)d_in[4];
    const float* qk_scale = (const float*)d_in[5];
    const float* w_out    = (const float*)d_in[6];
    float* out = (float*)d_out;

    float *p_qkv;
    __half *p_xnh, *p_xnl, *p_oh, *p_ol, *p_wqh, *p_wql, *p_woh, *p_wol;
    cudaGetSymbolAddress((void**)&p_qkv, g_qkv);
    cudaGetSymbolAddress((void**)&p_xnh, g_xnh);
    cudaGetSymbolAddress((void**)&p_xnl, g_xnl);
    cudaGetSymbolAddress((void**)&p_oh,  g_oh);
    cudaGetSymbolAddress((void**)&p_ol,  g_ol);
    cudaGetSymbolAddress((void**)&p_wqh, g_wqh);
    cudaGetSymbolAddress((void**)&p_wql, g_wql);
    cudaGetSymbolAddress((void**)&p_woh, g_woh);
    cudaGetSymbolAddress((void**)&p_wol, g_wol);

    static int s_attr = 0;
    if (!s_attr) {
        cudaFuncSetAttribute(attn_mma_kernel,
                             cudaFuncAttributeMaxDynamicSharedMemorySize, ATTN_SMEM);
        cudaFuncSetAttribute(mma_gemm_kernel,
                             cudaFuncAttributeMaxDynamicSharedMemorySize, GEMM_SMEM);
        s_attr = 1;
    }

    // Launch order puts the QKV GEMM at index 3 (the ncu-profiled slot).
    cond_gemm_kernel<<<dim3(DM/256, NB), 256>>>(cond, w_cond);
    rmsnorm_x_kernel<<<ROWS, 256>>>(x);
    split_kernel<<<(DM*3*DM + 255)/256, 256>>>(w_qkv, p_wqh, p_wql, DM*3*DM);
    mma_gemm_kernel<<<dim3(3*DM/128, ROWS/128), 256, GEMM_SMEM>>>(
        p_xnh, p_xnl, p_wqh, p_wql, p_qkv, ROWS, 3*DM, DM);
    split_kernel<<<(DM*DM + 255)/256, 256>>>(w_out, p_woh, p_wol, DM*DM);
    qknorm_rope_kernel<<<dim3(ROWS, NH/4), 128>>>(pos, qk_scale);
    attn_mma_kernel<<<dim3(SEQL/128, NH, NB), 128, ATTN_SMEM>>>();
    mma_gemm_kernel<<<dim3(DM/128, ROWS/128), 256, GEMM_SMEM>>>(
        p_oh, p_ol, p_woh, p_wol, out, ROWS, DM, DM);
}

// round 7
// speedup vs baseline: 4.9313x; 1.7015x over previous
#include <cuda_runtime.h>
#include <cuda_fp16.h>
#include <math.h>
#include <stdint.h>

// Problem shape: n=2, l=2048, d_model=1024, h=16, e=64
#define NB 2
#define SEQL 2048
#define DM 1024
#define NH 16
#define DE 64
#define ROWS (NB * SEQL)          // 4096

// ---------------- scratch ----------------
__device__ float  g_cwp[8 * NB * DM];         // cond partials
__device__ float  g_cw[NB * DM];
__device__ float  g_qkv[ROWS * 3 * DM];
__device__ __half g_xnh[ROWS * DM];
__device__ __half g_qh[NB*NH*SEQL*DE];
__device__ __half g_kh[NB*NH*SEQL*DE];
__device__ __half g_vh[NB*NH*SEQL*DE];
__device__ __half g_oh[ROWS * DM];
__device__ __half g_wqh[DM * 3 * DM], g_wql[DM * 3 * DM];
__device__ __half g_woh[DM * DM],     g_wol[DM * DM];

// ---------------- helpers ----------------
static __device__ __forceinline__ uint32_t smem_u32(const void* p) {
    uint32_t a;
    asm("{ .reg .u64 t; cvta.to.shared.u64 t, %1; cvt.u32.u64 %0, t; }" : "=r"(a) : "l"(p));
    return a;
}
static __device__ __forceinline__ void cpasync16(uint32_t dst, const void* src) {
    asm volatile("cp.async.cg.shared.global [%0], [%1], 16;" :: "r"(dst), "l"(src));
}
#define CP_COMMIT() asm volatile("cp.async.commit_group;" ::: "memory")
#define CP_WAIT1()  asm volatile("cp.async.wait_group 1;"  ::: "memory")
static __device__ __forceinline__ void ldsm4(uint32_t* r, uint32_t a) {
    asm volatile("ldmatrix.sync.aligned.m8n8.x4.shared.b16 {%0,%1,%2,%3}, [%4];"
        : "=r"(r[0]), "=r"(r[1]), "=r"(r[2]), "=r"(r[3]) : "r"(a));
}
static __device__ __forceinline__ void ldsm4t(uint32_t* r, uint32_t a) {
    asm volatile("ldmatrix.sync.aligned.m8n8.x4.trans.shared.b16 {%0,%1,%2,%3}, [%4];"
        : "=r"(r[0]), "=r"(r[1]), "=r"(r[2]), "=r"(r[3]) : "r"(a));
}
static __device__ __forceinline__ void mma_f16(float* c, const uint32_t* a, const uint32_t* b) {
    asm volatile("mma.sync.aligned.m16n8k16.row.col.f32.f16.f16.f32 "
        "{%0,%1,%2,%3}, {%4,%5,%6,%7}, {%8,%9}, {%0,%1,%2,%3};"
        : "+f"(c[0]), "+f"(c[1]), "+f"(c[2]), "+f"(c[3])
        : "r"(a[0]), "r"(a[1]), "r"(a[2]), "r"(a[3]), "r"(b[0]), "r"(b[1]));
}
static __device__ __forceinline__ float fast_exp2(float x) {
    float y; asm("ex2.approx.f32 %0, %1;" : "=f"(y) : "f"(x)); return y;
}
static __device__ __forceinline__ uint32_t packh(__half a, __half b) {
    return (uint32_t)__half_as_ushort(a) | ((uint32_t)__half_as_ushort(b) << 16);
}

// ---------------- split fp32 -> fp16 hi/lo (weights) ----------------
__global__ void split_kernel(const float* __restrict__ s, __half* __restrict__ h,
                             __half* __restrict__ l, int n)
{
    int i = blockIdx.x * blockDim.x + threadIdx.x;
    if (i < n) {
        float v = s[i];
        __half hh = __float2half_rn(v);
        h[i] = hh;
        l[i] = __float2half_rn(v - __half2float(hh));
    }
}

// ---------------- cond GEMM: K-split partials + reduce ----------------
__global__ void cond_partial_kernel(const float* __restrict__ cond,
                                    const float* __restrict__ w_cond)
{
    __shared__ float cs[128];
    const int n  = blockIdx.y;
    const int ks = blockIdx.z;
    if (threadIdx.x < 128)
        cs[threadIdx.x] = cond[n * DM + ks * 128 + threadIdx.x];
    __syncthreads();
    const int j = blockIdx.x * blockDim.x + threadIdx.x;
    float acc = 0.f;
#pragma unroll 8
    for (int k = 0; k < 128; k++)
        acc = fmaf(cs[k], w_cond[(size_t)(ks * 128 + k) * DM + j], acc);
    g_cwp[(ks * NB + n) * DM + j] = acc;
}
__global__ void cond_reduce_kernel()
{
    const int i = blockIdx.x * blockDim.x + threadIdx.x;   // 0..NB*DM-1
    const int n = i / DM, j = i % DM;
    float s = 1.0f;
#pragma unroll
    for (int ks = 0; ks < 8; ks++)
        s += g_cwp[(ks * NB + n) * DM + j];
    g_cw[i] = s;
}

// ---------------- xn = rms_norm(x, cw) -> fp16 hi ----------------
__global__ void rmsnorm_x_kernel(const float* __restrict__ x)
{
    const int row = blockIdx.x;
    const int n = row / SEQL;
    const int t = threadIdx.x;

    float4 v = *(const float4*)(x + (size_t)row * DM + t * 4);
    float ss = v.x * v.x + v.y * v.y + v.z * v.z + v.w * v.w;
#pragma unroll
    for (int o = 16; o > 0; o >>= 1)
        ss += __shfl_xor_sync(0xffffffffu, ss, o);

    __shared__ float ws[8];
    if ((t & 31) == 0) ws[t >> 5] = ss;
    __syncthreads();
    float tot = ws[0]+ws[1]+ws[2]+ws[3]+ws[4]+ws[5]+ws[6]+ws[7];
    float rinv = rsqrtf(tot * (1.0f / DM) + 1e-6f);

    float4 cwv = *(const float4*)(g_cw + n * DM + t * 4);
    size_t base = (size_t)row * DM + t * 4;
    *(uint32_t*)(g_xnh + base)     = packh(__float2half_rn(v.x * cwv.x * rinv),
                                           __float2half_rn(v.y * cwv.y * rinv));
    *(uint32_t*)(g_xnh + base + 2) = packh(__float2half_rn(v.z * cwv.z * rinv),
                                           __float2half_rn(v.w * cwv.w * rinv));
}

// ---------------- mma GEMM: C = Ah @ (Bh + Bl), 2-term ----------------
// BM=128, BN=128, BK=32, 256 threads (8 warps, 4x2), cp.async double buffer.
#define GM_ASTRIDE 80
#define GM_BSTRIDE 272
#define GM_A_SZ (128 * GM_ASTRIDE)            // 10240
#define GM_B_SZ (32 * GM_BSTRIDE)             // 8704
#define GM_BUF (GM_A_SZ + 2*GM_B_SZ)          // 27648
#define GEMM_SMEM (2 * GM_BUF)                // 55296

static __device__ __forceinline__ void gemm_load(uint32_t smb, int bufi,
    const __half* Ah, const __half* Bh, const __half* Bl,
    int m0, int n0, int k0, int K, int N, int tid)
{
    uint32_t base = smb + bufi * GM_BUF;
    const int ar = tid >> 1, ac = (tid & 1) * 16;       // halves
    const __half* pah = Ah + (size_t)(m0 + ar) * K + k0 + ac;
    cpasync16(base + ar*GM_ASTRIDE + ac*2,      pah);
    cpasync16(base + ar*GM_ASTRIDE + ac*2 + 16, pah + 8);
    const int br = tid >> 3, bc = (tid & 7) * 16;       // halves
    const __half* pbh = Bh + (size_t)(k0 + br) * N + n0 + bc;
    const __half* pbl = Bl + (size_t)(k0 + br) * N + n0 + bc;
    uint32_t bb = base + GM_A_SZ;
    cpasync16(bb + br*GM_BSTRIDE + bc*2,      pbh);
    cpasync16(bb + br*GM_BSTRIDE + bc*2 + 16, pbh + 8);
    cpasync16(bb + GM_B_SZ + br*GM_BSTRIDE + bc*2,      pbl);
    cpasync16(bb + GM_B_SZ + br*GM_BSTRIDE + bc*2 + 16, pbl + 8);
}

__global__ __launch_bounds__(256, 2) void mma_gemm_kernel(
    const __half* __restrict__ Ah,
    const __half* __restrict__ Bh, const __half* __restrict__ Bl,
    float* __restrict__ C, int M, int N, int K)
{
    extern __shared__ char sm[];
    const uint32_t smb = smem_u32(sm);
    const int tid = threadIdx.x, lane = tid & 31, wid = tid >> 5;
    const int m0 = blockIdx.y * 128, n0 = blockIdx.x * 128;
    const int wm = (wid & 3) * 32, wn = (wid >> 2) * 64;

    float acc[2][8][4];
#pragma unroll
    for (int m = 0; m < 2; m++)
#pragma unroll
        for (int n = 0; n < 8; n++)
#pragma unroll
            for (int r = 0; r < 4; r++) acc[m][n][r] = 0.f;

    gemm_load(smb, 0, Ah, Bh, Bl, m0, n0, 0, K, N, tid);
    CP_COMMIT();
    const int nk = K / 32;
    for (int s = 0; s < nk; s++) {
        if (s + 1 < nk)
            gemm_load(smb, (s + 1) & 1, Ah, Bh, Bl, m0, n0, (s + 1) * 32, K, N, tid);
        CP_COMMIT();
        CP_WAIT1();
        __syncthreads();

        uint32_t base = smb + (s & 1) * GM_BUF;
        uint32_t a_h = base;
        uint32_t b_h = base + GM_A_SZ, b_l = b_h + GM_B_SZ;
#pragma unroll
        for (int kt = 0; kt < 2; kt++) {
            uint32_t bfh[4][4], bfl[4][4];
            const uint32_t brow = kt * 16 + (lane & 7) + ((lane & 8) ? 8 : 0);
            const uint32_t bcol = wn * 2 + ((lane & 16) ? 16 : 0);
#pragma unroll
            for (int np = 0; np < 4; np++) {
                ldsm4t(bfh[np], b_h + brow * GM_BSTRIDE + bcol + np * 32);
                ldsm4t(bfl[np], b_l + brow * GM_BSTRIDE + bcol + np * 32);
            }
#pragma unroll
            for (int m = 0; m < 2; m++) {
                uint32_t afh[4];
                const uint32_t arow = wm + m * 16 + (lane & 15);
                const uint32_t acol = kt * 32 + ((lane & 16) ? 16 : 0);
                ldsm4(afh, a_h + arow * GM_ASTRIDE + acol);
#pragma unroll
                for (int np = 0; np < 4; np++) {
                    mma_f16(acc[m][2*np],   afh, bfh[np]);
                    mma_f16(acc[m][2*np+1], afh, bfh[np] + 2);
                    mma_f16(acc[m][2*np],   afh, bfl[np]);
                    mma_f16(acc[m][2*np+1], afh, bfl[np] + 2);
                }
            }
        }
        __syncthreads();
    }

    const int g = lane >> 2, tg = lane & 3;
#pragma unroll
    for (int m = 0; m < 2; m++)
#pragma unroll
        for (int rr = 0; rr < 2; rr++) {
            int row = m0 + wm + m * 16 + g + rr * 8;
#pragma unroll
            for (int n = 0; n < 8; n++) {
                int col = n0 + wn + n * 8 + tg * 2;
                float2 v = make_float2(acc[m][n][rr*2], acc[m][n][rr*2+1]);
                *(float2*)(C + (size_t)row * N + col) = v;
            }
        }
}

// ---------------- qk rmsnorm + rope -> fp16 Q,K,V ----------------
__global__ void qknorm_rope_kernel(const float* __restrict__ pos,
                                   const float* __restrict__ qk_scale)
{
    const int row  = blockIdx.x;
    const int n    = row / SEQL;
    const int l    = row % SEQL;
    const int warp = threadIdx.x >> 5;
    const int lane = threadIdx.x & 31;
    const int head = blockIdx.y * 4 + warp;

    const float* base = g_qkv + (size_t)row * (3 * DM);
    const int d1 = lane, d2 = lane + 32;

    float qa = base[head * DE + d1],          qb = base[head * DE + d2];
    float ka = base[DM + head * DE + d1],     kb = base[DM + head * DE + d2];
    float va = base[2 * DM + head * DE + d1], vb = base[2 * DM + head * DE + d2];

    float ssq = qa * qa + qb * qb;
    float ssk = ka * ka + kb * kb;
#pragma unroll
    for (int o = 16; o > 0; o >>= 1) {
        ssq += __shfl_xor_sync(0xffffffffu, ssq, o);
        ssk += __shfl_xor_sync(0xffffffffu, ssk, o);
    }

    float sc = expf(0.5f * fminf(qk_scale[head], 4.6051701860f) - 1.0397207708f);
    float rq = sc * rsqrtf(ssq * (1.0f / DE) + 1e-6f);
    float rk = sc * rsqrtf(ssk * (1.0f / DE) + 1e-6f);
    qa *= rq; qb *= rq; ka *= rk; kb *= rk;

    float pv = pos[(size_t)row * 2 + (lane >> 4)];
    int   j  = lane & 15;
    float fr = expf(1.14472988584940017f + (float)(j * 16 + head) * (2.30258509299404568f / 256.0f));
    float th = pv * fr;
    float cth = cosf(th), sth = sinf(th);

    float qo1 = qa * cth - qb * sth, qo2 = qb * cth + qa * sth;
    float ko1 = ka * cth - kb * sth, ko2 = kb * cth + ka * sth;

    size_t ob = ((size_t)(n * NH + head) * SEQL + l) * DE;
    g_qh[ob + d1] = __float2half_rn(qo1);
    g_qh[ob + d2] = __float2half_rn(qo2);
    g_kh[ob + d1] = __float2half_rn(ko1);
    g_kh[ob + d2] = __float2half_rn(ko2);
    g_vh[ob + d1] = __float2half_rn(va);
    g_vh[ob + d2] = __float2half_rn(vb);
}

// ---------------- attention via mma.sync (fp16 QKV, fp32 accum) ----------------
// CTA: 128 q-rows x (head,batch), 4 warps, TK=64 keys/tile, 32 tiles.
#define AT_STRIDE 144
#define AT_QH 0
#define AT_KV0 (128 * AT_STRIDE)              // 18432
#define AT_ARR (64 * AT_STRIDE)               // 9216 per array
#define AT_BUF (2 * AT_ARR)                   // 18432 (Kh, Vh)
#define ATTN_SMEM (AT_KV0 + 2 * AT_BUF)       // 55296

static __device__ __forceinline__ void attn_load_kv(uint32_t smb, size_t bh,
                                                    int tid, int t, int bufi)
{
    const int k0 = t * 64;
    const int r  = tid >> 1;
    const int hc = (tid & 1) * 32;
    uint32_t base = smb + AT_KV0 + bufi * AT_BUF + r * AT_STRIDE + hc * 2;
    const __half* s0 = g_kh + (bh + k0 + r) * DE + hc;
    const __half* s1 = g_vh + (bh + k0 + r) * DE + hc;
#pragma unroll
    for (int c = 0; c < 4; c++) {
        cpasync16(base + 0*AT_ARR + c*16, s0 + c*8);
        cpasync16(base + 1*AT_ARR + c*16, s1 + c*8);
    }
}

__global__ __launch_bounds__(128) void attn_mma_kernel()
{
    extern __shared__ char sm[];
    const uint32_t smb = smem_u32(sm);
    const int tid = threadIdx.x, lane = tid & 31, wid = tid >> 5;
    const int q0 = blockIdx.x * 128, head = blockIdx.y, b = blockIdx.z;
    const size_t bh = (size_t)(b * NH + head) * SEQL;
    const float SCL2 = 0.18033688011112042f;   // log2(e)/8

    // Q -> smem (own commit group)
    {
        const __half* qh = g_qh + (bh + q0 + tid) * DE;
        uint32_t dh = smb + AT_QH + tid * AT_STRIDE;
#pragma unroll
        for (int c = 0; c < 8; c++)
            cpasync16(dh + c*16, qh + c*8);
    }
    CP_COMMIT();
    attn_load_kv(smb, bh, tid, 0, 0);
    CP_COMMIT();
    CP_WAIT1();
    __syncthreads();

    // hoist Q fragments (loop-invariant)
    uint32_t qfr[2][4][4];
#pragma unroll
    for (int m = 0; m < 2; m++)
#pragma unroll
        for (int kt = 0; kt < 4; kt++) {
            const uint32_t qrow = wid*32 + m*16 + (lane & 15);
            const uint32_t qcol = kt * 32 + ((lane & 16) ? 16 : 0);
            ldsm4(qfr[m][kt], smb + AT_QH + qrow * AT_STRIDE + qcol);
        }

    float O[2][8][4];
#pragma unroll
    for (int m = 0; m < 2; m++)
#pragma unroll
        for (int n = 0; n < 8; n++)
#pragma unroll
            for (int r = 0; r < 4; r++) O[m][n][r] = 0.f;
    float ls[2][2] = {{0.f, 0.f}, {0.f, 0.f}};

    for (int t = 0; t < SEQL / 64; t++) {
        if (t + 1 < SEQL / 64) attn_load_kv(smb, bh, tid, t + 1, (t + 1) & 1);
        CP_COMMIT();
        CP_WAIT1();
        __syncthreads();

        uint32_t kb  = smb + AT_KV0 + (t & 1) * AT_BUF;
        uint32_t kh_b = kb, vh_b = kb + AT_ARR;

        float S[2][8][4];
#pragma unroll
        for (int m = 0; m < 2; m++)
#pragma unroll
            for (int n = 0; n < 8; n++)
#pragma unroll
                for (int r = 0; r < 4; r++) S[m][n][r] = 0.f;

        // ---- S = Q K^T ----
#pragma unroll
        for (int kt = 0; kt < 4; kt++) {
            uint32_t kfh[4][4];
            const uint32_t krow = (lane & 7) + ((lane & 16) ? 8 : 0);
            const uint32_t kcol = kt * 32 + ((lane & 8) ? 16 : 0);
#pragma unroll
            for (int np = 0; np < 4; np++)
                ldsm4(kfh[np], kh_b + (np*16 + krow) * AT_STRIDE + kcol);
#pragma unroll
            for (int m = 0; m < 2; m++)
#pragma unroll
                for (int np = 0; np < 4; np++) {
                    mma_f16(S[m][2*np],   qfr[m][kt], kfh[np]);
                    mma_f16(S[m][2*np+1], qfr[m][kt], kfh[np] + 2);
                }
        }

        // ---- P = exp(S/8) -> fp16 A-fragments (reg-to-reg) ----
        uint32_t pa[2][4][4];
#pragma unroll
        for (int m = 0; m < 2; m++)
#pragma unroll
            for (int n = 0; n < 8; n++) {
                float p0 = fast_exp2(S[m][n][0] * SCL2);
                float p1 = fast_exp2(S[m][n][1] * SCL2);
                float p2 = fast_exp2(S[m][n][2] * SCL2);
                float p3 = fast_exp2(S[m][n][3] * SCL2);
                ls[m][0] += p0 + p1;
                ls[m][1] += p2 + p3;
                const int kt = n >> 1, rb = (n & 1) * 2;
                pa[m][kt][rb]     = packh(__float2half_rn(p0), __float2half_rn(p1));
                pa[m][kt][rb + 1] = packh(__float2half_rn(p2), __float2half_rn(p3));
            }

        // ---- O += P V ----
#pragma unroll
        for (int kt = 0; kt < 4; kt++) {
            uint32_t vfh[4][4];
            const uint32_t vrow = kt*16 + (lane & 7) + ((lane & 8) ? 8 : 0);
            const uint32_t vcol = ((lane & 16) ? 16 : 0);
#pragma unroll
            for (int np = 0; np < 4; np++)
                ldsm4t(vfh[np], vh_b + vrow * AT_STRIDE + np*32 + vcol);
#pragma unroll
            for (int m = 0; m < 2; m++)
#pragma unroll
                for (int np = 0; np < 4; np++) {
                    mma_f16(O[m][2*np],   pa[m][kt], vfh[np]);
                    mma_f16(O[m][2*np+1], pa[m][kt], vfh[np] + 2);
                }
        }
        __syncthreads();
    }

    // ---- epilogue ----
#pragma unroll
    for (int m = 0; m < 2; m++)
#pragma unroll
        for (int r = 0; r < 2; r++) {
            ls[m][r] += __shfl_xor_sync(0xffffffffu, ls[m][r], 1);
            ls[m][r] += __shfl_xor_sync(0xffffffffu, ls[m][r], 2);
        }
    const int g = lane >> 2, tg = lane & 3;
#pragma unroll
    for (int m = 0; m < 2; m++) {
#pragma unroll
        for (int rr = 0; rr < 2; rr++) {
            const int row = q0 + wid*32 + m*16 + g + rr*8;
            const float inv = 1.0f / ls[m][rr];
            const size_t rb = ((size_t)b * SEQL + row) * DM + head * DE;
#pragma unroll
            for (int n = 0; n < 8; n++) {
                const int col = n*8 + tg*2;
                *(uint32_t*)(g_oh + rb + col) =
                    packh(__float2half_rn(O[m][n][rr*2]   * inv),
                          __float2half_rn(O[m][n][rr*2+1] * inv));
            }
        }
    }
}

// ---------------- launch ----------------
extern "C" void kernel_launch(void* const* d_in, const int* in_sizes, int n_in,
                              void* d_out, int out_size)
{
    const float* x        = (const float*)d_in[0];
    const float* pos      = (const float*)d_in[1];
    const float* cond     = (const float*)d_in[2];
    const float* w_cond   = (const float*)d_in[3];
    const float* w_qkv    = (const float*)d_in[4];
    const float* qk_scale = (const float*)d_in[5];
    const float* w_out    = (const float*)d_in[6];
    float* out = (float*)d_out;

    float *p_qkv;
    __half *p_xnh, *p_oh, *p_wqh, *p_wql, *p_woh, *p_wol;
    cudaGetSymbolAddress((void**)&p_qkv, g_qkv);
    cudaGetSymbolAddress((void**)&p_xnh, g_xnh);
    cudaGetSymbolAddress((void**)&p_oh,  g_oh);
    cudaGetSymbolAddress((void**)&p_wqh, g_wqh);
    cudaGetSymbolAddress((void**)&p_wql, g_wql);
    cudaGetSymbolAddress((void**)&p_woh, g_woh);
    cudaGetSymbolAddress((void**)&p_wol, g_wol);

    static int s_attr = 0;
    if (!s_attr) {
        cudaFuncSetAttribute(attn_mma_kernel,
                             cudaFuncAttributeMaxDynamicSharedMemorySize, ATTN_SMEM);
        cudaFuncSetAttribute(mma_gemm_kernel,
                             cudaFuncAttributeMaxDynamicSharedMemorySize, GEMM_SMEM);
        s_attr = 1;
    }

    cond_partial_kernel<<<dim3(DM/256, NB, 8), 256>>>(cond, w_cond);
    cond_reduce_kernel<<<NB*DM/256, 256>>>();
    split_kernel<<<(DM*3*DM + 255)/256, 256>>>(w_qkv, p_wqh, p_wql, DM*3*DM);
    rmsnorm_x_kernel<<<ROWS, 256>>>(x);
    mma_gemm_kernel<<<dim3(3*DM/128, ROWS/128), 256, GEMM_SMEM>>>(
        p_xnh, p_wqh, p_wql, p_qkv, ROWS, 3*DM, DM);
    qknorm_rope_kernel<<<dim3(ROWS, NH/4), 128>>>(pos, qk_scale);
    attn_mma_kernel<<<dim3(SEQL/128, NH, NB), 128, ATTN_SMEM>>>();
    split_kernel<<<(DM*DM + 255)/256, 256>>>(w_out, p_woh, p_wol, DM*DM);
    mma_gemm_kernel<<<dim3(DM/128, ROWS/128), 256, GEMM_SMEM>>>(
        p_oh, p_woh, p_wol, out, ROWS, DM, DM);
}

// round 8
// speedup vs baseline: 4.9775x; 1.0094x over previous
#include <cuda_runtime.h>
#include <cuda_fp16.h>
#include <math.h>
#include <stdint.h>

// Problem shape: n=2, l=2048, d_model=1024, h=16, e=64
#define NB 2
#define SEQL 2048
#define DM 1024
#define NH 16
#define DE 64
#define ROWS (NB * SEQL)          // 4096

// ---------------- scratch ----------------
__device__ float  g_cwp[8 * NB * DM];         // cond partials
__device__ float  g_cw[NB * DM];
__device__ __half g_qkv[ROWS * 3 * DM];
__device__ __half g_xnh[ROWS * DM];
__device__ __half g_qh[NB*NH*SEQL*DE];
__device__ __half g_kh[NB*NH*SEQL*DE];
__device__ __half g_vh[NB*NH*SEQL*DE];
__device__ __half g_oh[ROWS * DM];
__device__ __half g_wqh[DM * 3 * DM], g_wql[DM * 3 * DM];
__device__ __half g_woh[DM * DM],     g_wol[DM * DM];

// ---------------- helpers ----------------
static __device__ __forceinline__ uint32_t smem_u32(const void* p) {
    uint32_t a;
    asm("{ .reg .u64 t; cvta.to.shared.u64 t, %1; cvt.u32.u64 %0, t; }" : "=r"(a) : "l"(p));
    return a;
}
static __device__ __forceinline__ void cpasync16(uint32_t dst, const void* src) {
    asm volatile("cp.async.cg.shared.global [%0], [%1], 16;" :: "r"(dst), "l"(src));
}
#define CP_COMMIT() asm volatile("cp.async.commit_group;" ::: "memory")
#define CP_WAIT1()  asm volatile("cp.async.wait_group 1;"  ::: "memory")
static __device__ __forceinline__ void ldsm4(uint32_t* r, uint32_t a) {
    asm volatile("ldmatrix.sync.aligned.m8n8.x4.shared.b16 {%0,%1,%2,%3}, [%4];"
        : "=r"(r[0]), "=r"(r[1]), "=r"(r[2]), "=r"(r[3]) : "r"(a));
}
static __device__ __forceinline__ void ldsm4t(uint32_t* r, uint32_t a) {
    asm volatile("ldmatrix.sync.aligned.m8n8.x4.trans.shared.b16 {%0,%1,%2,%3}, [%4];"
        : "=r"(r[0]), "=r"(r[1]), "=r"(r[2]), "=r"(r[3]) : "r"(a));
}
static __device__ __forceinline__ void mma_f16(float* c, const uint32_t* a, const uint32_t* b) {
    asm volatile("mma.sync.aligned.m16n8k16.row.col.f32.f16.f16.f32 "
        "{%0,%1,%2,%3}, {%4,%5,%6,%7}, {%8,%9}, {%0,%1,%2,%3};"
        : "+f"(c[0]), "+f"(c[1]), "+f"(c[2]), "+f"(c[3])
        : "r"(a[0]), "r"(a[1]), "r"(a[2]), "r"(a[3]), "r"(b[0]), "r"(b[1]));
}
static __device__ __forceinline__ float fast_exp2(float x) {
    float y; asm("ex2.approx.f32 %0, %1;" : "=f"(y) : "f"(x)); return y;
}
static __device__ __forceinline__ uint32_t packh(__half a, __half b) {
    return (uint32_t)__half_as_ushort(a) | ((uint32_t)__half_as_ushort(b) << 16);
}

// ---------------- cond GEMM: K-split partials + reduce ----------------
__global__ void cond_partial_kernel(const float* __restrict__ cond,
                                    const float* __restrict__ w_cond)
{
    __shared__ float cs[128];
    const int n  = blockIdx.y;
    const int ks = blockIdx.z;
    if (threadIdx.x < 128)
        cs[threadIdx.x] = cond[n * DM + ks * 128 + threadIdx.x];
    __syncthreads();
    const int j = blockIdx.x * blockDim.x + threadIdx.x;
    float acc = 0.f;
#pragma unroll 8
    for (int k = 0; k < 128; k++)
        acc = fmaf(cs[k], w_cond[(size_t)(ks * 128 + k) * DM + j], acc);
    g_cwp[(ks * NB + n) * DM + j] = acc;
}
__global__ void cond_reduce_kernel()
{
    const int i = blockIdx.x * blockDim.x + threadIdx.x;
    const int n = i / DM, j = i % DM;
    float s = 1.0f;
#pragma unroll
    for (int ks = 0; ks < 8; ks++)
        s += g_cwp[(ks * NB + n) * DM + j];
    g_cw[i] = s;
}

// ---------------- fused: rmsnorm(x) + split(w_qkv) + split(w_out) ----------------
// blocks [0, 4096)               : rmsnorm rows
// blocks [4096, 4096+12288)      : w_qkv split (1 elem/thread)
// blocks [16384, 16384+4096)     : w_out split
#define FP_RMS   ROWS
#define FP_WQ    (DM * 3 * DM / 256)     // 12288
#define FP_WO    (DM * DM / 256)         // 4096
__global__ void fused_pre_kernel(const float* __restrict__ x,
                                 const float* __restrict__ w_qkv,
                                 const float* __restrict__ w_out)
{
    const int b = blockIdx.x;
    const int t = threadIdx.x;
    if (b < FP_RMS) {
        const int row = b;
        const int n = row / SEQL;
        float4 v = *(const float4*)(x + (size_t)row * DM + t * 4);
        float ss = v.x * v.x + v.y * v.y + v.z * v.z + v.w * v.w;
#pragma unroll
        for (int o = 16; o > 0; o >>= 1)
            ss += __shfl_xor_sync(0xffffffffu, ss, o);
        __shared__ float ws[8];
        if ((t & 31) == 0) ws[t >> 5] = ss;
        __syncthreads();
        float tot = ws[0]+ws[1]+ws[2]+ws[3]+ws[4]+ws[5]+ws[6]+ws[7];
        float rinv = rsqrtf(tot * (1.0f / DM) + 1e-6f);
        float4 cwv = *(const float4*)(g_cw + n * DM + t * 4);
        size_t base = (size_t)row * DM + t * 4;
        *(uint32_t*)(g_xnh + base)     = packh(__float2half_rn(v.x * cwv.x * rinv),
                                               __float2half_rn(v.y * cwv.y * rinv));
        *(uint32_t*)(g_xnh + base + 2) = packh(__float2half_rn(v.z * cwv.z * rinv),
                                               __float2half_rn(v.w * cwv.w * rinv));
    } else if (b < FP_RMS + FP_WQ) {
        int i = (b - FP_RMS) * 256 + t;
        float v = w_qkv[i];
        __half hh = __float2half_rn(v);
        g_wqh[i] = hh;
        g_wql[i] = __float2half_rn(v - __half2float(hh));
    } else {
        int i = (b - FP_RMS - FP_WQ) * 256 + t;
        float v = w_out[i];
        __half hh = __float2half_rn(v);
        g_woh[i] = hh;
        g_wol[i] = __float2half_rn(v - __half2float(hh));
    }
}

// ---------------- mma GEMM: C = Ah @ (Bh + Bl), 2-term, 3-stage ----------------
// BM=128, BN=128, BK=32, 256 threads (8 warps, 4x2).
#define GM_ASTRIDE 80
#define GM_BSTRIDE 272
#define GM_A_SZ (128 * GM_ASTRIDE)            // 10240
#define GM_B_SZ (32 * GM_BSTRIDE)             // 8704
#define GM_BUF (GM_A_SZ + 2*GM_B_SZ)          // 27648
#define GEMM_SMEM (3 * GM_BUF)                // 82944

static __device__ __forceinline__ void gemm_load(uint32_t smb, int bufi,
    const __half* Ah, const __half* Bh, const __half* Bl,
    int m0, int n0, int k0, int K, int N, int tid)
{
    uint32_t base = smb + bufi * GM_BUF;
    const int ar = tid >> 1, ac = (tid & 1) * 16;
    const __half* pah = Ah + (size_t)(m0 + ar) * K + k0 + ac;
    cpasync16(base + ar*GM_ASTRIDE + ac*2,      pah);
    cpasync16(base + ar*GM_ASTRIDE + ac*2 + 16, pah + 8);
    const int br = tid >> 3, bc = (tid & 7) * 16;
    const __half* pbh = Bh + (size_t)(k0 + br) * N + n0 + bc;
    const __half* pbl = Bl + (size_t)(k0 + br) * N + n0 + bc;
    uint32_t bb = base + GM_A_SZ;
    cpasync16(bb + br*GM_BSTRIDE + bc*2,      pbh);
    cpasync16(bb + br*GM_BSTRIDE + bc*2 + 16, pbh + 8);
    cpasync16(bb + GM_B_SZ + br*GM_BSTRIDE + bc*2,      pbl);
    cpasync16(bb + GM_B_SZ + br*GM_BSTRIDE + bc*2 + 16, pbl + 8);
}

template<int HOUT>
__global__ __launch_bounds__(256, 2) void mma_gemm_kernel(
    const __half* __restrict__ Ah,
    const __half* __restrict__ Bh, const __half* __restrict__ Bl,
    void* __restrict__ Cp, int M, int N, int K)
{
    extern __shared__ char sm[];
    const uint32_t smb = smem_u32(sm);
    const int tid = threadIdx.x, lane = tid & 31, wid = tid >> 5;
    const int m0 = blockIdx.y * 128, n0 = blockIdx.x * 128;
    const int wm = (wid & 3) * 32, wn = (wid >> 2) * 64;

    float acc[2][8][4];
#pragma unroll
    for (int m = 0; m < 2; m++)
#pragma unroll
        for (int n = 0; n < 8; n++)
#pragma unroll
            for (int r = 0; r < 4; r++) acc[m][n][r] = 0.f;

    const int nk = K / 32;
    gemm_load(smb, 0, Ah, Bh, Bl, m0, n0, 0, K, N, tid);
    CP_COMMIT();
    gemm_load(smb, 1, Ah, Bh, Bl, m0, n0, 32, K, N, tid);
    CP_COMMIT();

    for (int s = 0; s < nk; s++) {
        CP_WAIT1();                 // stage s resident, s+1 in flight
        __syncthreads();
        if (s + 2 < nk)
            gemm_load(smb, (s + 2) % 3, Ah, Bh, Bl, m0, n0, (s + 2) * 32, K, N, tid);
        CP_COMMIT();

        uint32_t base = smb + (s % 3) * GM_BUF;
        uint32_t a_h = base;
        uint32_t b_h = base + GM_A_SZ, b_l = b_h + GM_B_SZ;
#pragma unroll
        for (int kt = 0; kt < 2; kt++) {
            uint32_t bfh[4][4], bfl[4][4];
            const uint32_t brow = kt * 16 + (lane & 7) + ((lane & 8) ? 8 : 0);
            const uint32_t bcol = wn * 2 + ((lane & 16) ? 16 : 0);
#pragma unroll
            for (int np = 0; np < 4; np++) {
                ldsm4t(bfh[np], b_h + brow * GM_BSTRIDE + bcol + np * 32);
                ldsm4t(bfl[np], b_l + brow * GM_BSTRIDE + bcol + np * 32);
            }
#pragma unroll
            for (int m = 0; m < 2; m++) {
                uint32_t afh[4];
                const uint32_t arow = wm + m * 16 + (lane & 15);
                const uint32_t acol = kt * 32 + ((lane & 16) ? 16 : 0);
                ldsm4(afh, a_h + arow * GM_ASTRIDE + acol);
#pragma unroll
                for (int np = 0; np < 4; np++) {
                    mma_f16(acc[m][2*np],   afh, bfh[np]);
                    mma_f16(acc[m][2*np+1], afh, bfh[np] + 2);
                    mma_f16(acc[m][2*np],   afh, bfl[np]);
                    mma_f16(acc[m][2*np+1], afh, bfl[np] + 2);
                }
            }
        }
    }

    const int g = lane >> 2, tg = lane & 3;
#pragma unroll
    for (int m = 0; m < 2; m++)
#pragma unroll
        for (int rr = 0; rr < 2; rr++) {
            int row = m0 + wm + m * 16 + g + rr * 8;
#pragma unroll
            for (int n = 0; n < 8; n++) {
                int col = n0 + wn + n * 8 + tg * 2;
                if (HOUT) {
                    __half* C = (__half*)Cp;
                    *(uint32_t*)(C + (size_t)row * N + col) =
                        packh(__float2half_rn(acc[m][n][rr*2]),
                              __float2half_rn(acc[m][n][rr*2+1]));
                } else {
                    float* C = (float*)Cp;
                    *(float2*)(C + (size_t)row * N + col) =
                        make_float2(acc[m][n][rr*2], acc[m][n][rr*2+1]);
                }
            }
        }
}

// ---------------- qk rmsnorm + rope -> fp16 Q,K,V ----------------
__global__ void qknorm_rope_kernel(const float* __restrict__ pos,
                                   const float* __restrict__ qk_scale)
{
    const int row  = blockIdx.x;
    const int n    = row / SEQL;
    const int l    = row % SEQL;
    const int warp = threadIdx.x >> 5;
    const int lane = threadIdx.x & 31;
    const int head = blockIdx.y * 4 + warp;

    const __half* base = g_qkv + (size_t)row * (3 * DM);
    const int d1 = lane, d2 = lane + 32;

    float qa = __half2float(base[head * DE + d1]);
    float qb = __half2float(base[head * DE + d2]);
    float ka = __half2float(base[DM + head * DE + d1]);
    float kb = __half2float(base[DM + head * DE + d2]);
    __half va = base[2 * DM + head * DE + d1];
    __half vb = base[2 * DM + head * DE + d2];

    float ssq = qa * qa + qb * qb;
    float ssk = ka * ka + kb * kb;
#pragma unroll
    for (int o = 16; o > 0; o >>= 1) {
        ssq += __shfl_xor_sync(0xffffffffu, ssq, o);
        ssk += __shfl_xor_sync(0xffffffffu, ssk, o);
    }

    float sc = expf(0.5f * fminf(qk_scale[head], 4.6051701860f) - 1.0397207708f);
    float rq = sc * rsqrtf(ssq * (1.0f / DE) + 1e-6f);
    float rk = sc * rsqrtf(ssk * (1.0f / DE) + 1e-6f);
    qa *= rq; qb *= rq; ka *= rk; kb *= rk;

    float pv = pos[(size_t)row * 2 + (lane >> 4)];
    int   j  = lane & 15;
    float fr = expf(1.14472988584940017f + (float)(j * 16 + head) * (2.30258509299404568f / 256.0f));
    float th = pv * fr;
    float cth = cosf(th), sth = sinf(th);

    float qo1 = qa * cth - qb * sth, qo2 = qb * cth + qa * sth;
    float ko1 = ka * cth - kb * sth, ko2 = kb * cth + ka * sth;

    size_t ob = ((size_t)(n * NH + head) * SEQL + l) * DE;
    g_qh[ob + d1] = __float2half_rn(qo1);
    g_qh[ob + d2] = __float2half_rn(qo2);
    g_kh[ob + d1] = __float2half_rn(ko1);
    g_kh[ob + d2] = __float2half_rn(ko2);
    g_vh[ob + d1] = va;
    g_vh[ob + d2] = vb;
}

// ---------------- attention via mma.sync (fp16 QKV, fp32 accum), 3-stage ----------------
// CTA: 128 q-rows x (head,batch), 4 warps, TK=64 keys/tile, 32 tiles.
#define AT_STRIDE 144
#define AT_QH 0
#define AT_KV0 (128 * AT_STRIDE)              // 18432
#define AT_ARR (64 * AT_STRIDE)               // 9216 per array
#define AT_BUF (2 * AT_ARR)                   // 18432 (Kh, Vh)
#define NKT (SEQL / 64)                       // 32
#define ATTN_SMEM (AT_KV0 + 3 * AT_BUF)       // 73728

static __device__ __forceinline__ void attn_load_kv(uint32_t smb, size_t bh,
                                                    int tid, int t, int bufi)
{
    const int k0 = t * 64;
    const int r  = tid >> 1;
    const int hc = (tid & 1) * 32;
    uint32_t base = smb + AT_KV0 + bufi * AT_BUF + r * AT_STRIDE + hc * 2;
    const __half* s0 = g_kh + (bh + k0 + r) * DE + hc;
    const __half* s1 = g_vh + (bh + k0 + r) * DE + hc;
#pragma unroll
    for (int c = 0; c < 4; c++) {
        cpasync16(base + 0*AT_ARR + c*16, s0 + c*8);
        cpasync16(base + 1*AT_ARR + c*16, s1 + c*8);
    }
}

__global__ __launch_bounds__(128) void attn_mma_kernel()
{
    extern __shared__ char sm[];
    const uint32_t smb = smem_u32(sm);
    const int tid = threadIdx.x, lane = tid & 31, wid = tid >> 5;
    const int q0 = blockIdx.x * 128, head = blockIdx.y, b = blockIdx.z;
    const size_t bh = (size_t)(b * NH + head) * SEQL;
    const float SCL2 = 0.18033688011112042f;   // log2(e)/8

    // group 1: Q + kv0 ; group 2: kv1
    {
        const __half* qh = g_qh + (bh + q0 + tid) * DE;
        uint32_t dh = smb + AT_QH + tid * AT_STRIDE;
#pragma unroll
        for (int c = 0; c < 8; c++)
            cpasync16(dh + c*16, qh + c*8);
    }
    attn_load_kv(smb, bh, tid, 0, 0);
    CP_COMMIT();
    attn_load_kv(smb, bh, tid, 1, 1);
    CP_COMMIT();
    CP_WAIT1();                 // Q + kv0 resident
    __syncthreads();

    // hoist Q fragments (loop-invariant)
    uint32_t qfr[2][4][4];
#pragma unroll
    for (int m = 0; m < 2; m++)
#pragma unroll
        for (int kt = 0; kt < 4; kt++) {
            const uint32_t qrow = wid*32 + m*16 + (lane & 15);
            const uint32_t qcol = kt * 32 + ((lane & 16) ? 16 : 0);
            ldsm4(qfr[m][kt], smb + AT_QH + qrow * AT_STRIDE + qcol);
        }

    float O[2][8][4];
#pragma unroll
    for (int m = 0; m < 2; m++)
#pragma unroll
        for (int n = 0; n < 8; n++)
#pragma unroll
            for (int r = 0; r < 4; r++) O[m][n][r] = 0.f;
    float ls[2][2] = {{0.f, 0.f}, {0.f, 0.f}};

    for (int t = 0; t < NKT; t++) {
        CP_WAIT1();                 // kv(t) resident, kv(t+1) in flight
        __syncthreads();
        if (t + 2 < NKT)
            attn_load_kv(smb, bh, tid, t + 2, (t + 2) % 3);
        CP_COMMIT();

        uint32_t kb  = smb + AT_KV0 + (t % 3) * AT_BUF;
        uint32_t kh_b = kb, vh_b = kb + AT_ARR;

        float S[2][8][4];
#pragma unroll
        for (int m = 0; m < 2; m++)
#pragma unroll
            for (int n = 0; n < 8; n++)
#pragma unroll
                for (int r = 0; r < 4; r++) S[m][n][r] = 0.f;

        // ---- S = Q K^T ----
#pragma unroll
        for (int kt = 0; kt < 4; kt++) {
            uint32_t kfh[4][4];
            const uint32_t krow = (lane & 7) + ((lane & 16) ? 8 : 0);
            const uint32_t kcol = kt * 32 + ((lane & 8) ? 16 : 0);
#pragma unroll
            for (int np = 0; np < 4; np++)
                ldsm4(kfh[np], kh_b + (np*16 + krow) * AT_STRIDE + kcol);
#pragma unroll
            for (int m = 0; m < 2; m++)
#pragma unroll
                for (int np = 0; np < 4; np++) {
                    mma_f16(S[m][2*np],   qfr[m][kt], kfh[np]);
                    mma_f16(S[m][2*np+1], qfr[m][kt], kfh[np] + 2);
                }
        }

        // ---- P = exp(S/8) -> fp16 A-fragments (reg-to-reg) ----
        uint32_t pa[2][4][4];
#pragma unroll
        for (int m = 0; m < 2; m++)
#pragma unroll
            for (int n = 0; n < 8; n++) {
                float p0 = fast_exp2(S[m][n][0] * SCL2);
                float p1 = fast_exp2(S[m][n][1] * SCL2);
                float p2 = fast_exp2(S[m][n][2] * SCL2);
                float p3 = fast_exp2(S[m][n][3] * SCL2);
                ls[m][0] += p0 + p1;
                ls[m][1] += p2 + p3;
                const int kt = n >> 1, rb = (n & 1) * 2;
                pa[m][kt][rb]     = packh(__float2half_rn(p0), __float2half_rn(p1));
                pa[m][kt][rb + 1] = packh(__float2half_rn(p2), __float2half_rn(p3));
            }

        // ---- O += P V ----
#pragma unroll
        for (int kt = 0; kt < 4; kt++) {
            uint32_t vfh[4][4];
            const uint32_t vrow = kt*16 + (lane & 7) + ((lane & 8) ? 8 : 0);
            const uint32_t vcol = ((lane & 16) ? 16 : 0);
#pragma unroll
            for (int np = 0; np < 4; np++)
                ldsm4t(vfh[np], vh_b + vrow * AT_STRIDE + np*32 + vcol);
#pragma unroll
            for (int m = 0; m < 2; m++)
#pragma unroll
                for (int np = 0; np < 4; np++) {
                    mma_f16(O[m][2*np],   pa[m][kt], vfh[np]);
                    mma_f16(O[m][2*np+1], pa[m][kt], vfh[np] + 2);
                }
        }
    }

    // ---- epilogue ----
#pragma unroll
    for (int m = 0; m < 2; m++)
#pragma unroll
        for (int r = 0; r < 2; r++) {
            ls[m][r] += __shfl_xor_sync(0xffffffffu, ls[m][r], 1);
            ls[m][r] += __shfl_xor_sync(0xffffffffu, ls[m][r], 2);
        }
    const int g = lane >> 2, tg = lane & 3;
#pragma unroll
    for (int m = 0; m < 2; m++) {
#pragma unroll
        for (int rr = 0; rr < 2; rr++) {
            const int row = q0 + wid*32 + m*16 + g + rr*8;
            const float inv = 1.0f / ls[m][rr];
            const size_t rb = ((size_t)b * SEQL + row) * DM + head * DE;
#pragma unroll
            for (int n = 0; n < 8; n++) {
                const int col = n*8 + tg*2;
                *(uint32_t*)(g_oh + rb + col) =
                    packh(__float2half_rn(O[m][n][rr*2]   * inv),
                          __float2half_rn(O[m][n][rr*2+1] * inv));
            }
        }
    }
}

// ---------------- launch ----------------
extern "C" void kernel_launch(void* const* d_in, const int* in_sizes, int n_in,
                              void* d_out, int out_size)
{
    const float* x        = (const float*)d_in[0];
    const float* pos      = (const float*)d_in[1];
    const float* cond     = (const float*)d_in[2];
    const float* w_cond   = (const float*)d_in[3];
    const float* w_qkv    = (const float*)d_in[4];
    const float* qk_scale = (const float*)d_in[5];
    const float* w_out    = (const float*)d_in[6];
    float* out = (float*)d_out;

    __half *p_qkv, *p_xnh, *p_oh, *p_wqh, *p_wql, *p_woh, *p_wol;
    cudaGetSymbolAddress((void**)&p_qkv, g_qkv);
    cudaGetSymbolAddress((void**)&p_xnh, g_xnh);
    cudaGetSymbolAddress((void**)&p_oh,  g_oh);
    cudaGetSymbolAddress((void**)&p_wqh, g_wqh);
    cudaGetSymbolAddress((void**)&p_wql, g_wql);
    cudaGetSymbolAddress((void**)&p_woh, g_woh);
    cudaGetSymbolAddress((void**)&p_wol, g_wol);

    static int s_attr = 0;
    if (!s_attr) {
        cudaFuncSetAttribute(attn_mma_kernel,
                             cudaFuncAttributeMaxDynamicSharedMemorySize, ATTN_SMEM);
        cudaFuncSetAttribute(mma_gemm_kernel<1>,
                             cudaFuncAttributeMaxDynamicSharedMemorySize, GEMM_SMEM);
        cudaFuncSetAttribute(mma_gemm_kernel<0>,
                             cudaFuncAttributeMaxDynamicSharedMemorySize, GEMM_SMEM);
        s_attr = 1;
    }

    cond_partial_kernel<<<dim3(DM/256, NB, 8), 256>>>(cond, w_cond);         // 0
    cond_reduce_kernel<<<NB*DM/256, 256>>>();                                // 1
    fused_pre_kernel<<<FP_RMS + FP_WQ + FP_WO, 256>>>(x, w_qkv, w_out);      // 2
    mma_gemm_kernel<1><<<dim3(3*DM/128, ROWS/128), 256, GEMM_SMEM>>>(        // 3: QKV (profiled)
        p_xnh, p_wqh, p_wql, p_qkv, ROWS, 3*DM, DM);
    qknorm_rope_kernel<<<dim3(ROWS, NH/4), 128>>>(pos, qk_scale);            // 4
    attn_mma_kernel<<<dim3(SEQL/128, NH, NB), 128, ATTN_SMEM>>>();           // 5
    mma_gemm_kernel<0><<<dim3(DM/128, ROWS/128), 256, GEMM_SMEM>>>(          // 6: out
        p_oh, p_woh, p_wol, out, ROWS, DM, DM);
}